// round 1
// baseline (speedup 1.0000x reference)
#include <cuda_runtime.h>
#include <math.h>

// ---------------------------------------------------------------------------
// GlobalLocalAwareEncoder — truncated-dependency implementation.
//
// Key fact: dilated attention segments (64/128/256) are contiguous and
// non-overlapping, all aligned at multiples of 256. Output = seq_out[:, 0]
// depends only on tokens [0, 256) of the combined sequence. So we run the
// whole encoder on B=16 x S=256 tokens only (target + first 255 contexts).
// ---------------------------------------------------------------------------

#define BATCH   16
#define SEQ     256
#define TOK     (BATCH * SEQ)   // 4096
#define DIM     256
#define HEADS   8
#define HDIM    32
#define FFN_DIM 1024
#define INDIM   512
#define NCTX    4095

// Scratch (device globals — no allocation allowed)
__device__ float g_x  [TOK * DIM];
__device__ float g_h  [TOK * DIM];
__device__ float g_q  [TOK * DIM];
__device__ float g_k  [TOK * DIM];
__device__ float g_v  [TOK * DIM];
__device__ float g_acc[TOK * DIM];
__device__ float g_ffn[TOK * FFN_DIM];

__device__ __forceinline__ float gelu_tanh(float x) {
    float x3 = x * x * x;
    return 0.5f * x * (1.0f + tanhf(0.7978845608028654f * (x + 0.044715f * x3)));
}

// ---------------------------------------------------------------------------
// Generic fp32 GEMM: C[M,N] = A[M,K] @ B[K,N]  (+bias, +gelu, +residual)
// Tiles: BM=128, BN=64, BK=16. 256 threads, each computes 4x8.
// EPI: 0 = store, 1 = +bias, 2 = gelu(v+bias), 3 = res + v (+bias if non-null)
// ---------------------------------------------------------------------------
template<int EPI>
__global__ __launch_bounds__(256)
void gemm_kernel(const float* __restrict__ A, const float* __restrict__ B,
                 const float* __restrict__ bias, const float* __restrict__ res,
                 float* __restrict__ C, int M, int N, int K)
{
    __shared__ float As[128 * 17];
    __shared__ float Bs[16 * 64];

    const int t   = threadIdx.x;
    const int bm  = blockIdx.y * 128;
    const int bn  = blockIdx.x * 64;
    const int ty  = t >> 3;          // 0..31
    const int tx  = t & 7;           // 0..7
    const int row0 = ty * 4;
    const int col0 = tx * 8;

    float acc[4][8];
#pragma unroll
    for (int i = 0; i < 4; i++)
#pragma unroll
        for (int j = 0; j < 8; j++) acc[i][j] = 0.f;

    for (int k0 = 0; k0 < K; k0 += 16) {
#pragma unroll
        for (int i = 0; i < 8; i++) {
            int idx = t + 256 * i;          // 0..2047
            int m  = idx >> 4;
            int kk = idx & 15;
            As[m * 17 + kk] = A[(size_t)(bm + m) * K + k0 + kk];
        }
#pragma unroll
        for (int i = 0; i < 4; i++) {
            int idx = t + 256 * i;          // 0..1023
            int kk = idx >> 6;
            int n  = idx & 63;
            Bs[kk * 64 + n] = B[(size_t)(k0 + kk) * N + bn + n];
        }
        __syncthreads();
#pragma unroll
        for (int kk = 0; kk < 16; kk++) {
            float a0 = As[(row0 + 0) * 17 + kk];
            float a1 = As[(row0 + 1) * 17 + kk];
            float a2 = As[(row0 + 2) * 17 + kk];
            float a3 = As[(row0 + 3) * 17 + kk];
            float4 b0 = *(const float4*)&Bs[kk * 64 + col0];
            float4 b1 = *(const float4*)&Bs[kk * 64 + col0 + 4];
            float bv[8] = {b0.x, b0.y, b0.z, b0.w, b1.x, b1.y, b1.z, b1.w};
#pragma unroll
            for (int j = 0; j < 8; j++) {
                acc[0][j] += a0 * bv[j];
                acc[1][j] += a1 * bv[j];
                acc[2][j] += a2 * bv[j];
                acc[3][j] += a3 * bv[j];
            }
        }
        __syncthreads();
    }

#pragma unroll
    for (int i = 0; i < 4; i++) {
        size_t ridx = (size_t)(bm + row0 + i) * N + bn + col0;
        float vals[8];
#pragma unroll
        for (int j = 0; j < 8; j++) {
            float v = acc[i][j];
            if (EPI >= 1 && bias != nullptr) v += bias[bn + col0 + j];
            if (EPI == 2) v = gelu_tanh(v);
            if (EPI == 3) v += res[ridx + j];
            vals[j] = v;
        }
        *(float4*)&C[ridx]     = make_float4(vals[0], vals[1], vals[2], vals[3]);
        *(float4*)&C[ridx + 4] = make_float4(vals[4], vals[5], vals[6], vals[7]);
    }
}

// ---------------------------------------------------------------------------
// Projection GEMM: rows come from target_feat (s==0) or context_feats (s-1).
// C[4096,256] = X[4096,512] @ W_proj[512,256] + b_proj
// ---------------------------------------------------------------------------
__global__ __launch_bounds__(256)
void proj_gemm_kernel(const float* __restrict__ target_feat,
                      const float* __restrict__ context_feats,
                      const float* __restrict__ W, const float* __restrict__ bias,
                      float* __restrict__ C)
{
    __shared__ float As[128 * 17];
    __shared__ float Bs[16 * 64];

    const int t   = threadIdx.x;
    const int bm  = blockIdx.y * 128;
    const int bn  = blockIdx.x * 64;
    const int ty  = t >> 3;
    const int tx  = t & 7;
    const int row0 = ty * 4;
    const int col0 = tx * 8;
    const int N = DIM, K = INDIM;

    float acc[4][8];
#pragma unroll
    for (int i = 0; i < 4; i++)
#pragma unroll
        for (int j = 0; j < 8; j++) acc[i][j] = 0.f;

    for (int k0 = 0; k0 < K; k0 += 16) {
#pragma unroll
        for (int i = 0; i < 8; i++) {
            int idx = t + 256 * i;
            int m  = idx >> 4;
            int kk = idx & 15;
            int grow = bm + m;
            int b = grow >> 8;
            int s = grow & 255;
            const float* arow = (s == 0)
                ? (target_feat + (size_t)b * INDIM)
                : (context_feats + ((size_t)b * NCTX + (s - 1)) * INDIM);
            As[m * 17 + kk] = arow[k0 + kk];
        }
#pragma unroll
        for (int i = 0; i < 4; i++) {
            int idx = t + 256 * i;
            int kk = idx >> 6;
            int n  = idx & 63;
            Bs[kk * 64 + n] = W[(size_t)(k0 + kk) * N + bn + n];
        }
        __syncthreads();
#pragma unroll
        for (int kk = 0; kk < 16; kk++) {
            float a0 = As[(row0 + 0) * 17 + kk];
            float a1 = As[(row0 + 1) * 17 + kk];
            float a2 = As[(row0 + 2) * 17 + kk];
            float a3 = As[(row0 + 3) * 17 + kk];
            float4 b0 = *(const float4*)&Bs[kk * 64 + col0];
            float4 b1 = *(const float4*)&Bs[kk * 64 + col0 + 4];
            float bv[8] = {b0.x, b0.y, b0.z, b0.w, b1.x, b1.y, b1.z, b1.w};
#pragma unroll
            for (int j = 0; j < 8; j++) {
                acc[0][j] += a0 * bv[j];
                acc[1][j] += a1 * bv[j];
                acc[2][j] += a2 * bv[j];
                acc[3][j] += a3 * bv[j];
            }
        }
        __syncthreads();
    }

#pragma unroll
    for (int i = 0; i < 4; i++) {
        size_t ridx = (size_t)(bm + row0 + i) * N + bn + col0;
        float vals[8];
#pragma unroll
        for (int j = 0; j < 8; j++) vals[j] = acc[i][j] + bias[bn + col0 + j];
        *(float4*)&C[ridx]     = make_float4(vals[0], vals[1], vals[2], vals[3]);
        *(float4*)&C[ridx + 4] = make_float4(vals[4], vals[5], vals[6], vals[7]);
    }
}

// ---------------------------------------------------------------------------
// Add 0.3 * twoD_sincos(pos, 256). Layout: [sin_x(64), cos_x(64), sin_y(64), cos_y(64)]
// ---------------------------------------------------------------------------
__global__ void posenc_kernel(float* __restrict__ x,
                              const float* __restrict__ tpos,
                              const float* __restrict__ cpos)
{
    int idx = blockIdx.x * 256 + threadIdx.x;     // 0 .. TOK*DIM-1
    int tok = idx >> 8;
    int d   = idx & 255;
    int b   = tok >> 8;
    int s   = tok & 255;
    const float* pp = (s == 0) ? &tpos[(size_t)b * 2]
                               : &cpos[((size_t)b * NCTX + (s - 1)) * 2];
    float pos = (d < 128) ? pp[0] : pp[1];
    int dd = d & 127;
    int i  = dd & 63;
    // omega_i = 10000^{-i/64}
    float omega = expf(-(float)i * (9.210340371976184f / 64.0f));
    float ang = pos * omega;
    float pe = (dd < 64) ? sinf(ang) : cosf(ang);
    x[idx] += 0.3f * pe;
}

// ---------------------------------------------------------------------------
// LayerNorm: one warp per token, D=256 (8 floats/lane). Two-pass in registers.
// ---------------------------------------------------------------------------
__global__ void ln_kernel(const float* __restrict__ x, const float* __restrict__ sc,
                          const float* __restrict__ bi, float* __restrict__ out,
                          int ntok, int in_stride)
{
    int gw   = (blockIdx.x * blockDim.x + threadIdx.x) >> 5;
    int lane = threadIdx.x & 31;
    if (gw >= ntok) return;
    const float* xp = x + (size_t)gw * in_stride;
    float4 v0 = *(const float4*)&xp[lane * 4];
    float4 v1 = *(const float4*)&xp[128 + lane * 4];
    float va[8] = {v0.x, v0.y, v0.z, v0.w, v1.x, v1.y, v1.z, v1.w};

    float s = 0.f;
#pragma unroll
    for (int c = 0; c < 8; c++) s += va[c];
#pragma unroll
    for (int o = 16; o > 0; o >>= 1) s += __shfl_xor_sync(0xffffffffu, s, o);
    float mu = s * (1.0f / 256.0f);

    float ss = 0.f;
#pragma unroll
    for (int c = 0; c < 8; c++) { float dlt = va[c] - mu; ss += dlt * dlt; }
#pragma unroll
    for (int o = 16; o > 0; o >>= 1) ss += __shfl_xor_sync(0xffffffffu, ss, o);
    float inv = rsqrtf(ss * (1.0f / 256.0f) + 1e-5f);

    float ovals[8];
#pragma unroll
    for (int c = 0; c < 8; c++) {
        int d = (c < 4) ? (lane * 4 + c) : (128 + lane * 4 + (c - 4));
        ovals[c] = (va[c] - mu) * inv * sc[d] + bi[d];
    }
    float* op = out + (size_t)gw * 256;
    *(float4*)&op[lane * 4]       = make_float4(ovals[0], ovals[1], ovals[2], ovals[3]);
    *(float4*)&op[128 + lane * 4] = make_float4(ovals[4], ovals[5], ovals[6], ovals[7]);
}

// ---------------------------------------------------------------------------
// Dilated attention, one (batch, segment, head) block per CTA.
// m = w/r = 64 rows always. Gathered positions: seg*w + (h%r) + r*j.
// acc += (softmax(q k^T / sqrt(32)) v) / 3       (no collisions within launch)
// ---------------------------------------------------------------------------
__global__ __launch_bounds__(256)
void attn_kernel(const float* __restrict__ q, const float* __restrict__ k,
                 const float* __restrict__ v, float* __restrict__ acc,
                 int w, int r)
{
    __shared__ float qs[64 * 33];
    __shared__ float ks[64 * 33];
    __shared__ float vs[64 * 33];
    __shared__ float smP[64 * 65];

    const int nseg = SEQ / w;
    const int bid = blockIdx.x;
    const int h   = bid & 7;
    const int seg = (bid >> 3) % nseg;
    const int b   = bid / (8 * nseg);
    const int base = b * SEQ + seg * w;
    const int off  = h % r;
    const int t = threadIdx.x;

#pragma unroll
    for (int i = 0; i < 8; i++) {
        int idx = t + 256 * i;          // 0..2047
        int j = idx >> 5;
        int d = idx & 31;
        int tok = base + off + r * j;
        size_t gi = (size_t)tok * DIM + h * HDIM + d;
        qs[j * 33 + d] = q[gi];
        ks[j * 33 + d] = k[gi];
        vs[j * 33 + d] = v[gi];
    }
    __syncthreads();

    const int row = t >> 2;        // 0..63
    const int jo  = t & 3;

    float qreg[32];
#pragma unroll
    for (int d = 0; d < 32; d++) qreg[d] = qs[row * 33 + d];

    float s[16];
#pragma unroll
    for (int jj = 0; jj < 16; jj++) {
        int j = jo + 4 * jj;
        float dot = 0.f;
#pragma unroll
        for (int d = 0; d < 32; d++) dot += qreg[d] * ks[j * 33 + d];
        s[jj] = dot * 0.17677669529663687f;   // 1/sqrt(32)
    }

    float mx = s[0];
#pragma unroll
    for (int jj = 1; jj < 16; jj++) mx = fmaxf(mx, s[jj]);
    mx = fmaxf(mx, __shfl_xor_sync(0xffffffffu, mx, 1));
    mx = fmaxf(mx, __shfl_xor_sync(0xffffffffu, mx, 2));

    float sum = 0.f;
#pragma unroll
    for (int jj = 0; jj < 16; jj++) { s[jj] = __expf(s[jj] - mx); sum += s[jj]; }
    sum += __shfl_xor_sync(0xffffffffu, sum, 1);
    sum += __shfl_xor_sync(0xffffffffu, sum, 2);
    float invs = 1.0f / sum;

#pragma unroll
    for (int jj = 0; jj < 16; jj++) smP[row * 65 + jo + 4 * jj] = s[jj] * invs;
    __syncthreads();

    const int dg = (t & 3) * 8;
    float o[8];
#pragma unroll
    for (int d = 0; d < 8; d++) o[d] = 0.f;
    for (int j = 0; j < 64; j++) {
        float p = smP[row * 65 + j];
#pragma unroll
        for (int d = 0; d < 8; d++) o[d] += p * vs[j * 33 + dg + d];
    }
    int tok = base + off + r * row;
    float* ap = &acc[(size_t)tok * DIM + h * HDIM + dg];
#pragma unroll
    for (int d = 0; d < 8; d++) ap[d] += o[d] * (1.0f / 3.0f);
}

// ---------------------------------------------------------------------------
// Orchestration
// ---------------------------------------------------------------------------
extern "C" void kernel_launch(void* const* d_in, const int* in_sizes, int n_in,
                              void* d_out, int out_size)
{
    const float* target_feat   = (const float*)d_in[0];
    const float* context_feats = (const float*)d_in[1];
    const float* target_pos    = (const float*)d_in[2];
    const float* context_pos   = (const float*)d_in[3];
    const float* W_proj        = (const float*)d_in[4];
    const float* b_proj        = (const float*)d_in[5];
    const float* Wq            = (const float*)d_in[6];
    const float* Wk            = (const float*)d_in[7];
    const float* Wv            = (const float*)d_in[8];
    const float* Wo            = (const float*)d_in[9];
    const float* ln1_s         = (const float*)d_in[10];
    const float* ln1_b         = (const float*)d_in[11];
    const float* ln2_s         = (const float*)d_in[12];
    const float* ln2_b         = (const float*)d_in[13];
    const float* W1            = (const float*)d_in[14];
    const float* b1            = (const float*)d_in[15];
    const float* W2            = (const float*)d_in[16];
    const float* b2            = (const float*)d_in[17];
    const float* lnf_s         = (const float*)d_in[18];
    const float* lnf_b         = (const float*)d_in[19];
    float* out = (float*)d_out;

    float *x, *h, *q, *k, *v, *accb, *ffn;
    cudaGetSymbolAddress((void**)&x,    g_x);
    cudaGetSymbolAddress((void**)&h,    g_h);
    cudaGetSymbolAddress((void**)&q,    g_q);
    cudaGetSymbolAddress((void**)&k,    g_k);
    cudaGetSymbolAddress((void**)&v,    g_v);
    cudaGetSymbolAddress((void**)&accb, g_acc);
    cudaGetSymbolAddress((void**)&ffn,  g_ffn);

    const dim3 blk(256);
    const dim3 gN256(DIM / 64, TOK / 128);       // (4, 32)
    const dim3 gFFN(FFN_DIM / 64, TOK / 128);    // (16, 32)

    // Projection + positional encoding
    proj_gemm_kernel<<<gN256, blk>>>(target_feat, context_feats, W_proj, b_proj, x);
    posenc_kernel<<<TOK, 256>>>(x, target_pos, context_pos);

    for (int l = 0; l < 2; l++) {
        const float* wq = Wq + (size_t)l * DIM * DIM;
        const float* wk = Wk + (size_t)l * DIM * DIM;
        const float* wv = Wv + (size_t)l * DIM * DIM;
        const float* wo = Wo + (size_t)l * DIM * DIM;
        const float* w1 = W1 + (size_t)l * DIM * FFN_DIM;
        const float* w2 = W2 + (size_t)l * FFN_DIM * DIM;

        // LN1 -> h
        ln_kernel<<<(TOK * 32) / 256, 256>>>(x, ln1_s + l * DIM, ln1_b + l * DIM, h, TOK, DIM);

        // QKV
        gemm_kernel<0><<<gN256, blk>>>(h, wq, nullptr, nullptr, q, TOK, DIM, DIM);
        gemm_kernel<0><<<gN256, blk>>>(h, wk, nullptr, nullptr, k, TOK, DIM, DIM);
        gemm_kernel<0><<<gN256, blk>>>(h, wv, nullptr, nullptr, v, TOK, DIM, DIM);

        // Dilated attention (3 configs accumulate into acc)
        cudaMemsetAsync(accb, 0, (size_t)TOK * DIM * sizeof(float));
        attn_kernel<<<BATCH * 4 * HEADS, 256>>>(q, k, v, accb, 64, 1);
        attn_kernel<<<BATCH * 2 * HEADS, 256>>>(q, k, v, accb, 128, 2);
        attn_kernel<<<BATCH * 1 * HEADS, 256>>>(q, k, v, accb, 256, 4);

        // O projection + residual: x = x + acc @ Wo
        gemm_kernel<3><<<gN256, blk>>>(accb, wo, nullptr, x, x, TOK, DIM, DIM);

        // LN2 -> h
        ln_kernel<<<(TOK * 32) / 256, 256>>>(x, ln2_s + l * DIM, ln2_b + l * DIM, h, TOK, DIM);

        // FFN: ffn = gelu(h @ W1 + b1); x = x + ffn @ W2 + b2
        gemm_kernel<2><<<gFFN, blk>>>(h, w1, b1 + (size_t)l * FFN_DIM, nullptr, ffn, TOK, FFN_DIM, DIM);
        gemm_kernel<3><<<gN256, blk>>>(ffn, w2, b2 + (size_t)l * DIM, x, x, TOK, DIM, FFN_DIM);
    }

    // Final LN on token 0 of each batch -> out [16, 256]
    ln_kernel<<<2, 256>>>(x, lnf_s, lnf_b, out, BATCH, SEQ * DIM);
}

// round 2
// speedup vs baseline: 2.0351x; 2.0351x over previous
#include <cuda_runtime.h>
#include <math.h>

// ---------------------------------------------------------------------------
// GlobalLocalAwareEncoder — truncated-dependency implementation, tf32 MMA GEMMs.
//
// Dilated attention segments (64/128/256) are contiguous, non-overlapping,
// aligned at multiples of 256 -> output token 0 depends only on tokens [0,256)
// per batch. Run encoder on B=16 x S=256 tokens only.
//
// GEMMs use mma.sync.aligned.m16n8k8 tf32 with fp32 accumulate.
// ---------------------------------------------------------------------------

#define BATCH   16
#define SEQ     256
#define TOK     (BATCH * SEQ)   // 4096
#define DIM     256
#define HEADS   8
#define HDIM    32
#define FFN_DIM 1024
#define INDIM   512
#define NCTX    4095

// Scratch (device globals — no allocation allowed)
__device__ float g_x  [TOK * DIM];
__device__ float g_h  [TOK * DIM];
__device__ float g_q  [TOK * DIM];
__device__ float g_k  [TOK * DIM];
__device__ float g_v  [TOK * DIM];
__device__ float g_acc[TOK * DIM];
__device__ float g_ffn[TOK * FFN_DIM];

__device__ __forceinline__ float gelu_tanh(float x) {
    float x3 = x * x * x;
    return 0.5f * x * (1.0f + tanhf(0.7978845608028654f * (x + 0.044715f * x3)));
}

__device__ __forceinline__ unsigned f2tf32(float f) {
    unsigned u;
    asm("cvt.rna.tf32.f32 %0, %1;" : "=r"(u) : "f"(f));
    return u;
}

__device__ __forceinline__ void mma_tf32(float* d, uint4 a, unsigned b0, unsigned b1) {
    asm volatile(
        "mma.sync.aligned.m16n8k8.row.col.f32.tf32.tf32.f32 "
        "{%0,%1,%2,%3}, {%4,%5,%6,%7}, {%8,%9}, {%0,%1,%2,%3};"
        : "+f"(d[0]), "+f"(d[1]), "+f"(d[2]), "+f"(d[3])
        : "r"(a.x), "r"(a.y), "r"(a.z), "r"(a.w), "r"(b0), "r"(b1));
}

// positional encoding value for (token row, channel col), dim=256
__device__ __forceinline__ float pe_val(int row, int col,
                                        const float* __restrict__ tpos,
                                        const float* __restrict__ cpos) {
    int b = row >> 8, s = row & 255;
    const float* pp = (s == 0) ? (tpos + (size_t)b * 2)
                               : (cpos + ((size_t)b * NCTX + (s - 1)) * 2);
    float pos = (col < 128) ? pp[0] : pp[1];
    int dd = col & 127;
    int i  = dd & 63;
    float omega = expf(-(float)i * (9.210340371976184f / 64.0f));
    float ang = pos * omega;
    return (dd < 64) ? sinf(ang) : cosf(ang);
}

// ---------------------------------------------------------------------------
// tf32 MMA GEMM. C[4096,N] = A[4096,K] @ B[K,N], B row-major.
// CTA tile 64(M) x 128(N), BK=16, double-buffered. 256 threads = 8 warps,
// warp grid 2(M) x 4(N), warp tile 32x32, fragments m16n8k8.
//
// EPI: 0 = store
//      2 = gelu(v + bias)
//      3 = v + res (+ bias if non-null)
//      5 = v + bias + 0.3 * posenc       (projection)
// GATHER: A rows gathered from target_feat / context_feats (EPI 5 path).
// blockIdx.z selects (B0,C0)/(B1,C1)/(B2,C2) — used for fused QKV.
// ---------------------------------------------------------------------------
#define BS_STRIDE 136   // 16 rows x 136 floats (8*tig+gid bank pattern, conflict-free)

template<int EPI, bool GATHER>
__global__ __launch_bounds__(256)
void mma_gemm(const float* __restrict__ A,
              const float* __restrict__ B0, const float* __restrict__ B1,
              const float* __restrict__ B2,
              const float* __restrict__ bias, const float* __restrict__ res,
              float* __restrict__ C0, float* __restrict__ C1, float* __restrict__ C2,
              int N, int K,
              const float* __restrict__ tfeat, const float* __restrict__ cfeat,
              const float* __restrict__ tpos,  const float* __restrict__ cpos)
{
    __shared__ unsigned As[2][1024];            // [afrag(4)][kf(2)][lane(32)][4]
    __shared__ unsigned Bs[2][16 * BS_STRIDE];  // [k(16)][n(128)] padded

    const int z = blockIdx.z;
    const float* B = (z == 0) ? B0 : (z == 1) ? B1 : B2;
    float*       C = (z == 0) ? C0 : (z == 1) ? C1 : C2;

    const int t    = threadIdx.x;
    const int lane = t & 31;
    const int warp = t >> 5;
    const int wm   = warp >> 2;      // 0..1
    const int wn   = warp & 3;       // 0..3
    const int gid  = lane >> 2;      // 0..7
    const int tig  = lane & 3;       // 0..3

    const int bm = blockIdx.y * 64;
    const int bn = blockIdx.x * 128;

    // ---- A fill mapping (fragment order) ----
    const int a_mf = t >> 6;            // 0..3  (afrag)
    const int al   = t & 31;
    const int arow = a_mf * 16 + (al >> 2);      // local row (+8 for regs 1,3)
    const int acol = ((t >> 5) & 1) * 8 + (al & 3);  // local k (+4 for regs 2,3)

    const float *ap0, *ap1;
    if (GATHER) {
        int r0 = bm + arow;
        int r1 = r0 + 8;
        int b0i = r0 >> 8, s0 = r0 & 255;
        int b1i = r1 >> 8, s1 = r1 & 255;
        ap0 = (s0 == 0) ? (tfeat + (size_t)b0i * INDIM)
                        : (cfeat + ((size_t)b0i * NCTX + (s0 - 1)) * INDIM);
        ap1 = (s1 == 0) ? (tfeat + (size_t)b1i * INDIM)
                        : (cfeat + ((size_t)b1i * NCTX + (s1 - 1)) * INDIM);
    } else {
        ap0 = A + (size_t)(bm + arow) * K;
        ap1 = ap0 + (size_t)8 * K;
    }

    // ---- B fill mapping: 8 coalesced elements per thread ----
    int b_goff[8], b_soff[8];
#pragma unroll
    for (int i = 0; i < 8; i++) {
        int idx = t + 256 * i;
        int kk  = idx >> 7;      // 0..15
        int n   = idx & 127;
        b_goff[i] = kk * N + bn + n;
        b_soff[i] = kk * BS_STRIDE + n;
    }

    float accd[2][4][4];
#pragma unroll
    for (int mf = 0; mf < 2; mf++)
#pragma unroll
        for (int nf = 0; nf < 4; nf++)
#pragma unroll
            for (int r = 0; r < 4; r++) accd[mf][nf][r] = 0.f;

    const int nchunks = K >> 4;

    // prefetch registers
    float pa0, pa1, pa2, pa3;
    float pb[8];

    // load chunk 0
    {
        pa0 = ap0[acol];     pa1 = ap1[acol];
        pa2 = ap0[acol + 4]; pa3 = ap1[acol + 4];
        const float* bp = B;
#pragma unroll
        for (int i = 0; i < 8; i++) pb[i] = bp[b_goff[i]];
        unsigned* aw = &As[0][t * 4];
        aw[0] = f2tf32(pa0); aw[1] = f2tf32(pa1);
        aw[2] = f2tf32(pa2); aw[3] = f2tf32(pa3);
#pragma unroll
        for (int i = 0; i < 8; i++) Bs[0][b_soff[i]] = f2tf32(pb[i]);
    }
    __syncthreads();

    for (int c = 0; c < nchunks; c++) {
        const int s = c & 1;
        const bool more = (c + 1 < nchunks);
        if (more) {
            int k0 = (c + 1) << 4;
            pa0 = ap0[k0 + acol];     pa1 = ap1[k0 + acol];
            pa2 = ap0[k0 + acol + 4]; pa3 = ap1[k0 + acol + 4];
            const float* bp = B + (size_t)k0 * N;
#pragma unroll
            for (int i = 0; i < 8; i++) pb[i] = bp[b_goff[i]];
        }

        // compute on stage s
#pragma unroll
        for (int kf = 0; kf < 2; kf++) {
            uint4 afr[2];
            afr[0] = *(const uint4*)&As[s][(((wm * 2 + 0) * 2 + kf) * 32 + lane) * 4];
            afr[1] = *(const uint4*)&As[s][(((wm * 2 + 1) * 2 + kf) * 32 + lane) * 4];
#pragma unroll
            for (int nf = 0; nf < 4; nf++) {
                int cb = wn * 32 + nf * 8 + gid;
                unsigned bb0 = Bs[s][(kf * 8 + tig) * BS_STRIDE + cb];
                unsigned bb1 = Bs[s][(kf * 8 + tig + 4) * BS_STRIDE + cb];
                mma_tf32(accd[0][nf], afr[0], bb0, bb1);
                mma_tf32(accd[1][nf], afr[1], bb0, bb1);
            }
        }

        if (more) {
            const int s2 = s ^ 1;
            unsigned* aw = &As[s2][t * 4];
            aw[0] = f2tf32(pa0); aw[1] = f2tf32(pa1);
            aw[2] = f2tf32(pa2); aw[3] = f2tf32(pa3);
#pragma unroll
            for (int i = 0; i < 8; i++) Bs[s2][b_soff[i]] = f2tf32(pb[i]);
        }
        __syncthreads();
    }

    // ---- epilogue ----
#pragma unroll
    for (int mf = 0; mf < 2; mf++) {
#pragma unroll
        for (int nf = 0; nf < 4; nf++) {
            int row = bm + wm * 32 + mf * 16 + gid;
            int col = bn + wn * 32 + nf * 8 + 2 * tig;
#pragma unroll
            for (int half = 0; half < 2; half++) {
                int r = row + half * 8;
                float v0 = accd[mf][nf][half * 2 + 0];
                float v1 = accd[mf][nf][half * 2 + 1];
                size_t idx = (size_t)r * N + col;
                if (EPI == 2) {
                    v0 = gelu_tanh(v0 + bias[col]);
                    v1 = gelu_tanh(v1 + bias[col + 1]);
                } else if (EPI == 3) {
                    if (bias) { v0 += bias[col]; v1 += bias[col + 1]; }
                    v0 += res[idx]; v1 += res[idx + 1];
                } else if (EPI == 5) {
                    v0 += bias[col]     + 0.3f * pe_val(r, col,     tpos, cpos);
                    v1 += bias[col + 1] + 0.3f * pe_val(r, col + 1, tpos, cpos);
                }
                *(float2*)&C[idx] = make_float2(v0, v1);
            }
        }
    }
}

// ---------------------------------------------------------------------------
// LayerNorm: one warp per token, D=256 (8 floats/lane).
// ---------------------------------------------------------------------------
__global__ void ln_kernel(const float* __restrict__ x, const float* __restrict__ sc,
                          const float* __restrict__ bi, float* __restrict__ out,
                          int ntok, int in_stride)
{
    int gw   = (blockIdx.x * blockDim.x + threadIdx.x) >> 5;
    int lane = threadIdx.x & 31;
    if (gw >= ntok) return;
    const float* xp = x + (size_t)gw * in_stride;
    float4 v0 = *(const float4*)&xp[lane * 4];
    float4 v1 = *(const float4*)&xp[128 + lane * 4];
    float va[8] = {v0.x, v0.y, v0.z, v0.w, v1.x, v1.y, v1.z, v1.w};

    float s = 0.f;
#pragma unroll
    for (int c = 0; c < 8; c++) s += va[c];
#pragma unroll
    for (int o = 16; o > 0; o >>= 1) s += __shfl_xor_sync(0xffffffffu, s, o);
    float mu = s * (1.0f / 256.0f);

    float ss = 0.f;
#pragma unroll
    for (int c = 0; c < 8; c++) { float dlt = va[c] - mu; ss += dlt * dlt; }
#pragma unroll
    for (int o = 16; o > 0; o >>= 1) ss += __shfl_xor_sync(0xffffffffu, ss, o);
    float inv = rsqrtf(ss * (1.0f / 256.0f) + 1e-5f);

    float ovals[8];
#pragma unroll
    for (int c = 0; c < 8; c++) {
        int d = (c < 4) ? (lane * 4 + c) : (128 + lane * 4 + (c - 4));
        ovals[c] = (va[c] - mu) * inv * sc[d] + bi[d];
    }
    float* op = out + (size_t)gw * 256;
    *(float4*)&op[lane * 4]       = make_float4(ovals[0], ovals[1], ovals[2], ovals[3]);
    *(float4*)&op[128 + lane * 4] = make_float4(ovals[4], ovals[5], ovals[6], ovals[7]);
}

// ---------------------------------------------------------------------------
// Dilated attention, one (batch, segment, head) block per CTA.
// m = w/r = 64 rows always. Gathered positions: seg*w + (h%r) + r*j.
// ACC=false: acc = o/3 (first config).  ACC=true: acc += o/3.
// ---------------------------------------------------------------------------
template<bool ACC>
__global__ __launch_bounds__(256)
void attn_kernel(const float* __restrict__ q, const float* __restrict__ k,
                 const float* __restrict__ v, float* __restrict__ acc,
                 int w, int r)
{
    __shared__ float qs[64 * 33];
    __shared__ float ks[64 * 33];
    __shared__ float vs[64 * 33];
    __shared__ float smP[64 * 65];

    const int nseg = SEQ / w;
    const int bid = blockIdx.x;
    const int h   = bid & 7;
    const int seg = (bid >> 3) % nseg;
    const int b   = bid / (8 * nseg);
    const int base = b * SEQ + seg * w;
    const int off  = h % r;
    const int t = threadIdx.x;

#pragma unroll
    for (int i = 0; i < 8; i++) {
        int idx = t + 256 * i;          // 0..2047
        int j = idx >> 5;
        int d = idx & 31;
        int tok = base + off + r * j;
        size_t gi = (size_t)tok * DIM + h * HDIM + d;
        qs[j * 33 + d] = q[gi];
        ks[j * 33 + d] = k[gi];
        vs[j * 33 + d] = v[gi];
    }
    __syncthreads();

    const int row = t >> 2;        // 0..63
    const int jo  = t & 3;

    float qreg[32];
#pragma unroll
    for (int d = 0; d < 32; d++) qreg[d] = qs[row * 33 + d];

    float s[16];
#pragma unroll
    for (int jj = 0; jj < 16; jj++) {
        int j = jo + 4 * jj;
        float dot = 0.f;
#pragma unroll
        for (int d = 0; d < 32; d++) dot += qreg[d] * ks[j * 33 + d];
        s[jj] = dot * 0.17677669529663687f;   // 1/sqrt(32)
    }

    float mx = s[0];
#pragma unroll
    for (int jj = 1; jj < 16; jj++) mx = fmaxf(mx, s[jj]);
    mx = fmaxf(mx, __shfl_xor_sync(0xffffffffu, mx, 1));
    mx = fmaxf(mx, __shfl_xor_sync(0xffffffffu, mx, 2));

    float sum = 0.f;
#pragma unroll
    for (int jj = 0; jj < 16; jj++) { s[jj] = __expf(s[jj] - mx); sum += s[jj]; }
    sum += __shfl_xor_sync(0xffffffffu, sum, 1);
    sum += __shfl_xor_sync(0xffffffffu, sum, 2);
    float invs = 1.0f / sum;

#pragma unroll
    for (int jj = 0; jj < 16; jj++) smP[row * 65 + jo + 4 * jj] = s[jj] * invs;
    __syncthreads();

    const int dg = (t & 3) * 8;
    float o[8];
#pragma unroll
    for (int d = 0; d < 8; d++) o[d] = 0.f;
    for (int j = 0; j < 64; j++) {
        float p = smP[row * 65 + j];
#pragma unroll
        for (int d = 0; d < 8; d++) o[d] += p * vs[j * 33 + dg + d];
    }
    int tok = base + off + r * row;
    float* ap = &acc[(size_t)tok * DIM + h * HDIM + dg];
#pragma unroll
    for (int d = 0; d < 8; d++) {
        float val = o[d] * (1.0f / 3.0f);
        if (ACC) ap[d] += val; else ap[d] = val;
    }
}

// ---------------------------------------------------------------------------
// Orchestration
// ---------------------------------------------------------------------------
extern "C" void kernel_launch(void* const* d_in, const int* in_sizes, int n_in,
                              void* d_out, int out_size)
{
    const float* target_feat   = (const float*)d_in[0];
    const float* context_feats = (const float*)d_in[1];
    const float* target_pos    = (const float*)d_in[2];
    const float* context_pos   = (const float*)d_in[3];
    const float* W_proj        = (const float*)d_in[4];
    const float* b_proj        = (const float*)d_in[5];
    const float* Wq            = (const float*)d_in[6];
    const float* Wk            = (const float*)d_in[7];
    const float* Wv            = (const float*)d_in[8];
    const float* Wo            = (const float*)d_in[9];
    const float* ln1_s         = (const float*)d_in[10];
    const float* ln1_b         = (const float*)d_in[11];
    const float* ln2_s         = (const float*)d_in[12];
    const float* ln2_b         = (const float*)d_in[13];
    const float* W1            = (const float*)d_in[14];
    const float* b1            = (const float*)d_in[15];
    const float* W2            = (const float*)d_in[16];
    const float* b2            = (const float*)d_in[17];
    const float* lnf_s         = (const float*)d_in[18];
    const float* lnf_b         = (const float*)d_in[19];
    float* out = (float*)d_out;

    float *x, *h, *q, *k, *v, *accb, *ffn;
    cudaGetSymbolAddress((void**)&x,    g_x);
    cudaGetSymbolAddress((void**)&h,    g_h);
    cudaGetSymbolAddress((void**)&q,    g_q);
    cudaGetSymbolAddress((void**)&k,    g_k);
    cudaGetSymbolAddress((void**)&v,    g_v);
    cudaGetSymbolAddress((void**)&accb, g_acc);
    cudaGetSymbolAddress((void**)&ffn,  g_ffn);

    const dim3 blk(256);
    const dim3 gProj(DIM / 128, TOK / 64, 1);      // (2, 64)
    const dim3 gQKV (DIM / 128, TOK / 64, 3);      // (2, 64, 3)
    const dim3 gN   (DIM / 128, TOK / 64, 1);      // (2, 64)
    const dim3 gFFN (FFN_DIM / 128, TOK / 64, 1);  // (8, 64)

    // Projection (+bias +posenc fused)
    mma_gemm<5, true><<<gProj, blk>>>(nullptr, W_proj, nullptr, nullptr,
                                      b_proj, nullptr, x, nullptr, nullptr,
                                      DIM, INDIM,
                                      target_feat, context_feats, target_pos, context_pos);

    for (int l = 0; l < 2; l++) {
        const float* wq = Wq + (size_t)l * DIM * DIM;
        const float* wk = Wk + (size_t)l * DIM * DIM;
        const float* wv = Wv + (size_t)l * DIM * DIM;
        const float* wo = Wo + (size_t)l * DIM * DIM;
        const float* w1 = W1 + (size_t)l * DIM * FFN_DIM;
        const float* w2 = W2 + (size_t)l * FFN_DIM * DIM;

        // LN1 -> h
        ln_kernel<<<(TOK * 32) / 256, 256>>>(x, ln1_s + l * DIM, ln1_b + l * DIM, h, TOK, DIM);

        // QKV fused (blockIdx.z selects weight/output)
        mma_gemm<0, false><<<gQKV, blk>>>(h, wq, wk, wv, nullptr, nullptr,
                                          q, k, v, DIM, DIM,
                                          nullptr, nullptr, nullptr, nullptr);

        // Dilated attention (first writes, rest accumulate)
        attn_kernel<false><<<BATCH * 4 * HEADS, 256>>>(q, k, v, accb, 64, 1);
        attn_kernel<true ><<<BATCH * 2 * HEADS, 256>>>(q, k, v, accb, 128, 2);
        attn_kernel<true ><<<BATCH * 1 * HEADS, 256>>>(q, k, v, accb, 256, 4);

        // O projection + residual: x = x + acc @ Wo
        mma_gemm<3, false><<<gN, blk>>>(accb, wo, nullptr, nullptr, nullptr, x,
                                        x, nullptr, nullptr, DIM, DIM,
                                        nullptr, nullptr, nullptr, nullptr);

        // LN2 -> h
        ln_kernel<<<(TOK * 32) / 256, 256>>>(x, ln2_s + l * DIM, ln2_b + l * DIM, h, TOK, DIM);

        // FFN: ffn = gelu(h @ W1 + b1); x = x + ffn @ W2 + b2
        mma_gemm<2, false><<<gFFN, blk>>>(h, w1, nullptr, nullptr,
                                          b1 + (size_t)l * FFN_DIM, nullptr,
                                          ffn, nullptr, nullptr, FFN_DIM, DIM,
                                          nullptr, nullptr, nullptr, nullptr);
        mma_gemm<3, false><<<gN, blk>>>(ffn, w2, nullptr, nullptr,
                                        b2 + (size_t)l * DIM, x,
                                        x, nullptr, nullptr, DIM, FFN_DIM,
                                        nullptr, nullptr, nullptr, nullptr);
    }

    // Final LN on token 0 of each batch -> out [16, 256]
    ln_kernel<<<2, 256>>>(x, lnf_s, lnf_b, out, BATCH, SEQ * DIM);
}

// round 3
// speedup vs baseline: 2.2937x; 1.1271x over previous
#include <cuda_runtime.h>
#include <math.h>

// ---------------------------------------------------------------------------
// GlobalLocalAwareEncoder — truncated-dependency implementation, tf32 MMA GEMMs.
//
// Truncation 1: dilated attention segments (64/128/256) are contiguous,
// non-overlapping, aligned at multiples of 256 -> output token 0 depends only
// on tokens [0,256) per batch. Run encoder on B=16 x S=256 tokens only.
//
// Truncation 2: layer 2 is the last layer; only token 0 of each batch feeds
// the output. So layer-2 FFN / Wo / Q are M=16 GEMMs, and layer-2 attention
// is 224 single-row softmaxes (head h contributes from config r iff h%r==0).
// ---------------------------------------------------------------------------

#define BATCH   16
#define SEQ     256
#define TOK     (BATCH * SEQ)   // 4096
#define DIM     256
#define HEADS   8
#define HDIM    32
#define FFN_DIM 1024
#define INDIM   512
#define NCTX    4095

// Scratch (device globals — no allocation allowed)
__device__ float g_x  [TOK * DIM];
__device__ float g_h  [TOK * DIM];
__device__ float g_q  [TOK * DIM];
__device__ float g_k  [TOK * DIM];
__device__ float g_v  [TOK * DIM];
__device__ float g_acc[TOK * DIM];
__device__ float g_ffn[TOK * FFN_DIM];

__device__ __forceinline__ float gelu_tanh(float x) {
    float x3 = x * x * x;
    return 0.5f * x * (1.0f + tanhf(0.7978845608028654f * (x + 0.044715f * x3)));
}

__device__ __forceinline__ unsigned f2tf32(float f) {
    unsigned u;
    asm("cvt.rna.tf32.f32 %0, %1;" : "=r"(u) : "f"(f));
    return u;
}

__device__ __forceinline__ void mma_tf32(float* d, uint4 a, unsigned b0, unsigned b1) {
    asm volatile(
        "mma.sync.aligned.m16n8k8.row.col.f32.tf32.tf32.f32 "
        "{%0,%1,%2,%3}, {%4,%5,%6,%7}, {%8,%9}, {%0,%1,%2,%3};"
        : "+f"(d[0]), "+f"(d[1]), "+f"(d[2]), "+f"(d[3])
        : "r"(a.x), "r"(a.y), "r"(a.z), "r"(a.w), "r"(b0), "r"(b1));
}

// positional encoding value for (token row, channel col), dim=256
__device__ __forceinline__ float pe_val(int row, int col,
                                        const float* __restrict__ tpos,
                                        const float* __restrict__ cpos) {
    int b = row >> 8, s = row & 255;
    const float* pp = (s == 0) ? (tpos + (size_t)b * 2)
                               : (cpos + ((size_t)b * NCTX + (s - 1)) * 2);
    float pos = (col < 128) ? pp[0] : pp[1];
    int dd = col & 127;
    int i  = dd & 63;
    float omega = expf(-(float)i * (9.210340371976184f / 64.0f));
    float ang = pos * omega;
    return (dd < 64) ? sinf(ang) : cosf(ang);
}

// ---------------------------------------------------------------------------
// tf32 MMA GEMM. C[4096,N] = A[4096,K] @ B[K,N], B row-major.
// CTA tile 64(M) x 128(N), BK=16, double-buffered. 256 threads = 8 warps,
// warp grid 2(M) x 4(N), warp tile 32x32, fragments m16n8k8.
// EPI: 0 store / 2 gelu(v+bias) / 3 v+res(+bias) / 5 v+bias+0.3*posenc
// ---------------------------------------------------------------------------
#define BS_STRIDE 136

template<int EPI, bool GATHER>
__global__ __launch_bounds__(256)
void mma_gemm(const float* __restrict__ A,
              const float* __restrict__ B0, const float* __restrict__ B1,
              const float* __restrict__ B2,
              const float* __restrict__ bias, const float* __restrict__ res,
              float* __restrict__ C0, float* __restrict__ C1, float* __restrict__ C2,
              int N, int K,
              const float* __restrict__ tfeat, const float* __restrict__ cfeat,
              const float* __restrict__ tpos,  const float* __restrict__ cpos)
{
    __shared__ unsigned As[2][1024];
    __shared__ unsigned Bs[2][16 * BS_STRIDE];

    const int z = blockIdx.z;
    const float* B = (z == 0) ? B0 : (z == 1) ? B1 : B2;
    float*       C = (z == 0) ? C0 : (z == 1) ? C1 : C2;

    const int t    = threadIdx.x;
    const int lane = t & 31;
    const int warp = t >> 5;
    const int wm   = warp >> 2;
    const int wn   = warp & 3;
    const int gid  = lane >> 2;
    const int tig  = lane & 3;

    const int bm = blockIdx.y * 64;
    const int bn = blockIdx.x * 128;

    const int a_mf = t >> 6;
    const int al   = t & 31;
    const int arow = a_mf * 16 + (al >> 2);
    const int acol = ((t >> 5) & 1) * 8 + (al & 3);

    const float *ap0, *ap1;
    if (GATHER) {
        int r0 = bm + arow;
        int r1 = r0 + 8;
        int b0i = r0 >> 8, s0 = r0 & 255;
        int b1i = r1 >> 8, s1 = r1 & 255;
        ap0 = (s0 == 0) ? (tfeat + (size_t)b0i * INDIM)
                        : (cfeat + ((size_t)b0i * NCTX + (s0 - 1)) * INDIM);
        ap1 = (s1 == 0) ? (tfeat + (size_t)b1i * INDIM)
                        : (cfeat + ((size_t)b1i * NCTX + (s1 - 1)) * INDIM);
    } else {
        ap0 = A + (size_t)(bm + arow) * K;
        ap1 = ap0 + (size_t)8 * K;
    }

    int b_goff[8], b_soff[8];
#pragma unroll
    for (int i = 0; i < 8; i++) {
        int idx = t + 256 * i;
        int kk  = idx >> 7;
        int n   = idx & 127;
        b_goff[i] = kk * N + bn + n;
        b_soff[i] = kk * BS_STRIDE + n;
    }

    float accd[2][4][4];
#pragma unroll
    for (int mf = 0; mf < 2; mf++)
#pragma unroll
        for (int nf = 0; nf < 4; nf++)
#pragma unroll
            for (int r = 0; r < 4; r++) accd[mf][nf][r] = 0.f;

    const int nchunks = K >> 4;
    float pa0, pa1, pa2, pa3;
    float pb[8];

    {
        pa0 = ap0[acol];     pa1 = ap1[acol];
        pa2 = ap0[acol + 4]; pa3 = ap1[acol + 4];
        const float* bp = B;
#pragma unroll
        for (int i = 0; i < 8; i++) pb[i] = bp[b_goff[i]];
        unsigned* aw = &As[0][t * 4];
        aw[0] = f2tf32(pa0); aw[1] = f2tf32(pa1);
        aw[2] = f2tf32(pa2); aw[3] = f2tf32(pa3);
#pragma unroll
        for (int i = 0; i < 8; i++) Bs[0][b_soff[i]] = f2tf32(pb[i]);
    }
    __syncthreads();

    for (int c = 0; c < nchunks; c++) {
        const int s = c & 1;
        const bool more = (c + 1 < nchunks);
        if (more) {
            int k0 = (c + 1) << 4;
            pa0 = ap0[k0 + acol];     pa1 = ap1[k0 + acol];
            pa2 = ap0[k0 + acol + 4]; pa3 = ap1[k0 + acol + 4];
            const float* bp = B + (size_t)k0 * N;
#pragma unroll
            for (int i = 0; i < 8; i++) pb[i] = bp[b_goff[i]];
        }

#pragma unroll
        for (int kf = 0; kf < 2; kf++) {
            uint4 afr[2];
            afr[0] = *(const uint4*)&As[s][(((wm * 2 + 0) * 2 + kf) * 32 + lane) * 4];
            afr[1] = *(const uint4*)&As[s][(((wm * 2 + 1) * 2 + kf) * 32 + lane) * 4];
#pragma unroll
            for (int nf = 0; nf < 4; nf++) {
                int cb = wn * 32 + nf * 8 + gid;
                unsigned bb0 = Bs[s][(kf * 8 + tig) * BS_STRIDE + cb];
                unsigned bb1 = Bs[s][(kf * 8 + tig + 4) * BS_STRIDE + cb];
                mma_tf32(accd[0][nf], afr[0], bb0, bb1);
                mma_tf32(accd[1][nf], afr[1], bb0, bb1);
            }
        }

        if (more) {
            const int s2 = s ^ 1;
            unsigned* aw = &As[s2][t * 4];
            aw[0] = f2tf32(pa0); aw[1] = f2tf32(pa1);
            aw[2] = f2tf32(pa2); aw[3] = f2tf32(pa3);
#pragma unroll
            for (int i = 0; i < 8; i++) Bs[s2][b_soff[i]] = f2tf32(pb[i]);
        }
        __syncthreads();
    }

#pragma unroll
    for (int mf = 0; mf < 2; mf++) {
#pragma unroll
        for (int nf = 0; nf < 4; nf++) {
            int row = bm + wm * 32 + mf * 16 + gid;
            int col = bn + wn * 32 + nf * 8 + 2 * tig;
#pragma unroll
            for (int half = 0; half < 2; half++) {
                int r = row + half * 8;
                float v0 = accd[mf][nf][half * 2 + 0];
                float v1 = accd[mf][nf][half * 2 + 1];
                size_t idx = (size_t)r * N + col;
                if (EPI == 2) {
                    v0 = gelu_tanh(v0 + bias[col]);
                    v1 = gelu_tanh(v1 + bias[col + 1]);
                } else if (EPI == 3) {
                    if (bias) { v0 += bias[col]; v1 += bias[col + 1]; }
                    v0 += res[idx]; v1 += res[idx + 1];
                } else if (EPI == 5) {
                    v0 += bias[col]     + 0.3f * pe_val(r, col,     tpos, cpos);
                    v1 += bias[col + 1] + 0.3f * pe_val(r, col + 1, tpos, cpos);
                }
                *(float2*)&C[idx] = make_float2(v0, v1);
            }
        }
    }
}

// ---------------------------------------------------------------------------
// Small GEMM for layer-2 M=16 paths. C[16,N] = A[16,K] @ B[K,N].
// A rows at stride lda, C rows at stride ldc (token-0 rows may be strided).
// 256 threads: col = t&31 (+32*blockIdx.x), half = m-split, ks = 4-way K split
// (interleaved), reduced through smem. fp32 FFMA (more accurate than tf32).
// ---------------------------------------------------------------------------
template<int EPI>
__global__ __launch_bounds__(256)
void small_gemm(const float* __restrict__ A, size_t lda,
                const float* __restrict__ B,
                const float* __restrict__ bias, const float* __restrict__ res,
                float* __restrict__ C, size_t ldc, int N, int K)
{
    __shared__ float As[256 * 17 / 16];   // placeholder avoided below
    (void)As;
}

// real implementation (non-template shared layout)
template<int EPI>
__global__ __launch_bounds__(256)
void small_gemm_k(const float* __restrict__ A, size_t lda,
                  const float* __restrict__ B,
                  const float* __restrict__ bias, const float* __restrict__ res,
                  float* __restrict__ C, size_t ldc, int N, int K)
{
    __shared__ float Ash[256 * 17];       // [kk][m], stride 17
    __shared__ float red[4 * 32 * 16];    // [ks][colL][m]

    const int t    = threadIdx.x;
    const int colL = t & 31;
    const int col  = blockIdx.x * 32 + colL;
    const int rest = t >> 5;          // 0..7
    const int half = rest & 1;
    const int ks   = rest >> 1;       // 0..3

    float acc[8];
#pragma unroll
    for (int m = 0; m < 8; m++) acc[m] = 0.f;

    for (int c0 = 0; c0 < K; c0 += 256) {
        // coalesced A load: 16 rows x 256 k
#pragma unroll
        for (int m = 0; m < 16; m++)
            Ash[t * 17 + m] = A[(size_t)m * lda + c0 + t];
        __syncthreads();
        for (int kk = ks; kk < 256; kk += 4) {
            float b = B[(size_t)(c0 + kk) * N + col];
#pragma unroll
            for (int m = 0; m < 8; m++)
                acc[m] += Ash[kk * 17 + half * 8 + m] * b;
        }
        __syncthreads();
    }

    float* rp = &red[(ks * 32 + colL) * 16 + half * 8];
#pragma unroll
    for (int m = 0; m < 8; m++) rp[m] = acc[m];
    __syncthreads();

    const int mO = t >> 5;   // 0..7 -> handles m = mO and mO+8
#pragma unroll
    for (int mm = mO; mm < 16; mm += 8) {
        float v = red[(0 * 32 + colL) * 16 + mm] + red[(1 * 32 + colL) * 16 + mm]
                + red[(2 * 32 + colL) * 16 + mm] + red[(3 * 32 + colL) * 16 + mm];
        if (EPI == 2) v = gelu_tanh(v + bias[col]);
        else if (EPI == 3) { if (bias) v += bias[col]; v += res[(size_t)mm * ldc + col]; }
        C[(size_t)mm * ldc + col] = v;
    }
}

// ---------------------------------------------------------------------------
// LayerNorm: one warp per token, D=256 (8 floats/lane).
// ---------------------------------------------------------------------------
__global__ void ln_kernel(const float* __restrict__ x, const float* __restrict__ sc,
                          const float* __restrict__ bi, float* __restrict__ out,
                          int ntok, int in_stride)
{
    int gw   = (blockIdx.x * blockDim.x + threadIdx.x) >> 5;
    int lane = threadIdx.x & 31;
    if (gw >= ntok) return;
    const float* xp = x + (size_t)gw * in_stride;
    float4 v0 = *(const float4*)&xp[lane * 4];
    float4 v1 = *(const float4*)&xp[128 + lane * 4];
    float va[8] = {v0.x, v0.y, v0.z, v0.w, v1.x, v1.y, v1.z, v1.w};

    float s = 0.f;
#pragma unroll
    for (int c = 0; c < 8; c++) s += va[c];
#pragma unroll
    for (int o = 16; o > 0; o >>= 1) s += __shfl_xor_sync(0xffffffffu, s, o);
    float mu = s * (1.0f / 256.0f);

    float ss = 0.f;
#pragma unroll
    for (int c = 0; c < 8; c++) { float dlt = va[c] - mu; ss += dlt * dlt; }
#pragma unroll
    for (int o = 16; o > 0; o >>= 1) ss += __shfl_xor_sync(0xffffffffu, ss, o);
    float inv = rsqrtf(ss * (1.0f / 256.0f) + 1e-5f);

    float ovals[8];
#pragma unroll
    for (int c = 0; c < 8; c++) {
        int d = (c < 4) ? (lane * 4 + c) : (128 + lane * 4 + (c - 4));
        ovals[c] = (va[c] - mu) * inv * sc[d] + bi[d];
    }
    float* op = out + (size_t)gw * 256;
    *(float4*)&op[lane * 4]       = make_float4(ovals[0], ovals[1], ovals[2], ovals[3]);
    *(float4*)&op[128 + lane * 4] = make_float4(ovals[4], ovals[5], ovals[6], ovals[7]);
}

// ---------------------------------------------------------------------------
// Layer-1 dilated attention, one (batch, segment, head) block per CTA.
// Vectorized smem (stride 36 -> LDS.128, conflict-free).
// ---------------------------------------------------------------------------
template<bool ACC>
__global__ __launch_bounds__(256)
void attn_kernel(const float* __restrict__ q, const float* __restrict__ k,
                 const float* __restrict__ v, float* __restrict__ acc,
                 int w, int r)
{
    __shared__ float qs[64 * 36];
    __shared__ float ks[64 * 36];
    __shared__ float vs[64 * 36];
    __shared__ float smP[64 * 65];

    const int nseg = SEQ / w;
    const int bid = blockIdx.x;
    const int h   = bid & 7;
    const int seg = (bid >> 3) % nseg;
    const int b   = bid / (8 * nseg);
    const int base = b * SEQ + seg * w;
    const int off  = h % r;
    const int t = threadIdx.x;

    // fill: 512 float4 per array
#pragma unroll
    for (int i = 0; i < 2; i++) {
        int idx = t + 256 * i;          // 0..511
        int j  = idx >> 3;
        int dq = (idx & 7) * 4;
        int tok = base + off + r * j;
        size_t gi = (size_t)tok * DIM + h * HDIM + dq;
        *(float4*)&qs[j * 36 + dq] = *(const float4*)&q[gi];
        *(float4*)&ks[j * 36 + dq] = *(const float4*)&k[gi];
        *(float4*)&vs[j * 36 + dq] = *(const float4*)&v[gi];
    }
    __syncthreads();

    // QK: thread = (rowpair rp = t>>3, jo = t&7): rows {rp, rp+32}, j = jo+8*jj
    {
        const int rp = t >> 3;
        const int jo = t & 7;
        float4 qa[8], qb[8];
#pragma unroll
        for (int u = 0; u < 8; u++) {
            qa[u] = *(const float4*)&qs[rp * 36 + u * 4];
            qb[u] = *(const float4*)&qs[(rp + 32) * 36 + u * 4];
        }
        float s0[8], s1[8];
#pragma unroll
        for (int jj = 0; jj < 8; jj++) {
            int j = jo + 8 * jj;
            float d0 = 0.f, d1 = 0.f;
#pragma unroll
            for (int u = 0; u < 8; u++) {
                float4 kv = *(const float4*)&ks[j * 36 + u * 4];
                d0 += qa[u].x * kv.x + qa[u].y * kv.y + qa[u].z * kv.z + qa[u].w * kv.w;
                d1 += qb[u].x * kv.x + qb[u].y * kv.y + qb[u].z * kv.z + qb[u].w * kv.w;
            }
            s0[jj] = d0 * 0.17677669529663687f;
            s1[jj] = d1 * 0.17677669529663687f;
        }

        float m0 = s0[0], m1 = s1[0];
#pragma unroll
        for (int jj = 1; jj < 8; jj++) { m0 = fmaxf(m0, s0[jj]); m1 = fmaxf(m1, s1[jj]); }
#pragma unroll
        for (int o = 4; o > 0; o >>= 1) {
            m0 = fmaxf(m0, __shfl_xor_sync(0xffffffffu, m0, o));
            m1 = fmaxf(m1, __shfl_xor_sync(0xffffffffu, m1, o));
        }
        float su0 = 0.f, su1 = 0.f;
#pragma unroll
        for (int jj = 0; jj < 8; jj++) {
            s0[jj] = __expf(s0[jj] - m0); su0 += s0[jj];
            s1[jj] = __expf(s1[jj] - m1); su1 += s1[jj];
        }
#pragma unroll
        for (int o = 4; o > 0; o >>= 1) {
            su0 += __shfl_xor_sync(0xffffffffu, su0, o);
            su1 += __shfl_xor_sync(0xffffffffu, su1, o);
        }
        float i0 = 1.0f / su0, i1 = 1.0f / su1;
#pragma unroll
        for (int jj = 0; jj < 8; jj++) {
            int j = jo + 8 * jj;
            smP[rp * 65 + j]        = s0[jj] * i0;
            smP[(rp + 32) * 65 + j] = s1[jj] * i1;
        }
    }
    __syncthreads();

    // PV: thread = (row = t>>2, dg = (t&3)*8)
    {
        const int row = t >> 2;
        const int dg  = (t & 3) * 8;
        float4 o0 = make_float4(0.f, 0.f, 0.f, 0.f);
        float4 o1 = make_float4(0.f, 0.f, 0.f, 0.f);
#pragma unroll 4
        for (int j = 0; j < 64; j++) {
            float p = smP[row * 65 + j];
            float4 va = *(const float4*)&vs[j * 36 + dg];
            float4 vb = *(const float4*)&vs[j * 36 + dg + 4];
            o0.x += p * va.x; o0.y += p * va.y; o0.z += p * va.z; o0.w += p * va.w;
            o1.x += p * vb.x; o1.y += p * vb.y; o1.z += p * vb.z; o1.w += p * vb.w;
        }
        const float third = 1.0f / 3.0f;
        int tok = base + off + r * row;
        float* ap = &acc[(size_t)tok * DIM + h * HDIM + dg];
        if (ACC) {
            float4 a0 = *(float4*)&ap[0];
            float4 a1 = *(float4*)&ap[4];
            a0.x += o0.x * third; a0.y += o0.y * third; a0.z += o0.z * third; a0.w += o0.w * third;
            a1.x += o1.x * third; a1.y += o1.y * third; a1.z += o1.z * third; a1.w += o1.w * third;
            *(float4*)&ap[0] = a0; *(float4*)&ap[4] = a1;
        } else {
            *(float4*)&ap[0] = make_float4(o0.x * third, o0.y * third, o0.z * third, o0.w * third);
            *(float4*)&ap[4] = make_float4(o1.x * third, o1.y * third, o1.z * third, o1.w * third);
        }
    }
}

// ---------------------------------------------------------------------------
// Layer-2 attention: only token 0 per batch matters. One CTA per batch,
// one warp per head. Head h contributes from config (w,r) iff h%r==0, and
// token 0 is row j=0 of segment 0 (keys at tokens r*j, j=0..63).
// Writes acc at token-0 rows only (complete value, overwrite).
// ---------------------------------------------------------------------------
__global__ __launch_bounds__(256)
void attn_tok0_kernel(const float* __restrict__ q16,
                      const float* __restrict__ k, const float* __restrict__ v,
                      float* __restrict__ acc)
{
    __shared__ float psh[8][64];
    __shared__ float qsh[8][33];

    const int b    = blockIdx.x;
    const int h    = threadIdx.x >> 5;
    const int lane = threadIdx.x & 31;

    qsh[h][lane] = q16[b * 256 + h * 32 + lane];
    __syncwarp();

    const int rs[3] = {1, 2, 4};
    float o = 0.f;

#pragma unroll
    for (int c = 0; c < 3; c++) {
        int r = rs[c];
        if (h % r) continue;

        const float* k0p = k + ((size_t)(b * 256 + r * lane) * DIM) + h * 32;
        const float* k1p = k + ((size_t)(b * 256 + r * (lane + 32)) * DIM) + h * 32;
        float s0 = 0.f, s1 = 0.f;
#pragma unroll
        for (int d = 0; d < 32; d++) {
            float qd = qsh[h][d];
            s0 += qd * k0p[d];
            s1 += qd * k1p[d];
        }
        s0 *= 0.17677669529663687f;
        s1 *= 0.17677669529663687f;

        float mx = fmaxf(s0, s1);
#pragma unroll
        for (int ofs = 16; ofs > 0; ofs >>= 1)
            mx = fmaxf(mx, __shfl_xor_sync(0xffffffffu, mx, ofs));
        float e0 = __expf(s0 - mx), e1 = __expf(s1 - mx);
        float sm = e0 + e1;
#pragma unroll
        for (int ofs = 16; ofs > 0; ofs >>= 1)
            sm += __shfl_xor_sync(0xffffffffu, sm, ofs);
        float inv = 1.0f / sm;
        psh[h][lane]      = e0 * inv;
        psh[h][lane + 32] = e1 * inv;
        __syncwarp();

        float oc = 0.f;
#pragma unroll 8
        for (int j = 0; j < 64; j++)
            oc += psh[h][j] * v[((size_t)(b * 256 + r * j) * DIM) + h * 32 + lane];
        o += oc;
        __syncwarp();
    }

    acc[(size_t)b * SEQ * DIM + h * 32 + lane] = o * (1.0f / 3.0f);
}

// ---------------------------------------------------------------------------
// Orchestration
// ---------------------------------------------------------------------------
extern "C" void kernel_launch(void* const* d_in, const int* in_sizes, int n_in,
                              void* d_out, int out_size)
{
    const float* target_feat   = (const float*)d_in[0];
    const float* context_feats = (const float*)d_in[1];
    const float* target_pos    = (const float*)d_in[2];
    const float* context_pos   = (const float*)d_in[3];
    const float* W_proj        = (const float*)d_in[4];
    const float* b_proj        = (const float*)d_in[5];
    const float* Wq            = (const float*)d_in[6];
    const float* Wk            = (const float*)d_in[7];
    const float* Wv            = (const float*)d_in[8];
    const float* Wo            = (const float*)d_in[9];
    const float* ln1_s         = (const float*)d_in[10];
    const float* ln1_b         = (const float*)d_in[11];
    const float* ln2_s         = (const float*)d_in[12];
    const float* ln2_b         = (const float*)d_in[13];
    const float* W1            = (const float*)d_in[14];
    const float* b1            = (const float*)d_in[15];
    const float* W2            = (const float*)d_in[16];
    const float* b2            = (const float*)d_in[17];
    const float* lnf_s         = (const float*)d_in[18];
    const float* lnf_b         = (const float*)d_in[19];
    float* out = (float*)d_out;

    float *x, *h, *q, *k, *v, *accb, *ffn;
    cudaGetSymbolAddress((void**)&x,    g_x);
    cudaGetSymbolAddress((void**)&h,    g_h);
    cudaGetSymbolAddress((void**)&q,    g_q);
    cudaGetSymbolAddress((void**)&k,    g_k);
    cudaGetSymbolAddress((void**)&v,    g_v);
    cudaGetSymbolAddress((void**)&accb, g_acc);
    cudaGetSymbolAddress((void**)&ffn,  g_ffn);

    const dim3 blk(256);
    const dim3 gProj(DIM / 128, TOK / 64, 1);
    const dim3 gQKV (DIM / 128, TOK / 64, 3);
    const dim3 gKV  (DIM / 128, TOK / 64, 2);
    const dim3 gN   (DIM / 128, TOK / 64, 1);
    const dim3 gFFN (FFN_DIM / 128, TOK / 64, 1);
    const size_t ROWSTRIDE = (size_t)SEQ * DIM;   // token-0 row stride in x

    // Projection (+bias +posenc fused)
    mma_gemm<5, true><<<gProj, blk>>>(nullptr, W_proj, nullptr, nullptr,
                                      b_proj, nullptr, x, nullptr, nullptr,
                                      DIM, INDIM,
                                      target_feat, context_feats, target_pos, context_pos);

    // ======================= Layer 1 (full) =======================
    {
        const float* wq = Wq;
        const float* wk = Wk;
        const float* wv = Wv;
        const float* wo = Wo;
        const float* w1 = W1;
        const float* w2 = W2;

        ln_kernel<<<(TOK * 32) / 256, 256>>>(x, ln1_s, ln1_b, h, TOK, DIM);

        mma_gemm<0, false><<<gQKV, blk>>>(h, wq, wk, wv, nullptr, nullptr,
                                          q, k, v, DIM, DIM,
                                          nullptr, nullptr, nullptr, nullptr);

        attn_kernel<false><<<BATCH * 4 * HEADS, 256>>>(q, k, v, accb, 64, 1);
        attn_kernel<true ><<<BATCH * 2 * HEADS, 256>>>(q, k, v, accb, 128, 2);
        attn_kernel<true ><<<BATCH * 1 * HEADS, 256>>>(q, k, v, accb, 256, 4);

        mma_gemm<3, false><<<gN, blk>>>(accb, wo, nullptr, nullptr, nullptr, x,
                                        x, nullptr, nullptr, DIM, DIM,
                                        nullptr, nullptr, nullptr, nullptr);

        ln_kernel<<<(TOK * 32) / 256, 256>>>(x, ln2_s, ln2_b, h, TOK, DIM);

        mma_gemm<2, false><<<gFFN, blk>>>(h, w1, nullptr, nullptr,
                                          b1, nullptr,
                                          ffn, nullptr, nullptr, FFN_DIM, DIM,
                                          nullptr, nullptr, nullptr, nullptr);
        mma_gemm<3, false><<<gN, blk>>>(ffn, w2, nullptr, nullptr,
                                        b2, x,
                                        x, nullptr, nullptr, DIM, FFN_DIM,
                                        nullptr, nullptr, nullptr, nullptr);
    }

    // ================== Layer 2 (token-0 truncated) ==================
    {
        const float* wq = Wq + (size_t)1 * DIM * DIM;
        const float* wk = Wk + (size_t)1 * DIM * DIM;
        const float* wv = Wv + (size_t)1 * DIM * DIM;
        const float* wo = Wo + (size_t)1 * DIM * DIM;
        const float* w1 = W1 + (size_t)1 * DIM * FFN_DIM;
        const float* w2 = W2 + (size_t)1 * FFN_DIM * DIM;

        // LN1 full (K,V need all tokens)
        ln_kernel<<<(TOK * 32) / 256, 256>>>(x, ln1_s + DIM, ln1_b + DIM, h, TOK, DIM);

        // K,V full (fused z=2)
        mma_gemm<0, false><<<gKV, blk>>>(h, wk, wv, nullptr, nullptr, nullptr,
                                         k, v, nullptr, DIM, DIM,
                                         nullptr, nullptr, nullptr, nullptr);

        // Q only for token 0 of each batch -> q16 = g_q[0:16*256]
        small_gemm_k<0><<<DIM / 32, 256>>>(h, ROWSTRIDE, wq, nullptr, nullptr,
                                           q, (size_t)DIM, DIM, DIM);

        // attention for token 0 rows -> acc token-0 rows
        attn_tok0_kernel<<<BATCH, 256>>>(q, k, v, accb);

        // Wo + residual on token-0 rows (strided in/out)
        small_gemm_k<3><<<DIM / 32, 256>>>(accb, ROWSTRIDE, wo, nullptr, x,
                                           x, ROWSTRIDE, DIM, DIM);

        // LN2 on 16 token-0 rows -> h16 (contiguous at g_h)
        ln_kernel<<<2, 256>>>(x, ln2_s + DIM, ln2_b + DIM, h, BATCH, SEQ * DIM);

        // FFN on 16 rows
        small_gemm_k<2><<<FFN_DIM / 32, 256>>>(h, (size_t)DIM, w1,
                                               b1 + FFN_DIM, nullptr,
                                               ffn, (size_t)FFN_DIM, FFN_DIM, DIM);
        small_gemm_k<3><<<DIM / 32, 256>>>(ffn, (size_t)FFN_DIM, w2,
                                           b2 + DIM, x,
                                           x, ROWSTRIDE, DIM, FFN_DIM);
    }

    // Final LN on token 0 of each batch -> out [16, 256]
    ln_kernel<<<2, 256>>>(x, lnf_s, lnf_b, out, BATCH, SEQ * DIM);
}

// round 4
// speedup vs baseline: 2.7510x; 1.1993x over previous
#include <cuda_runtime.h>
#include <math.h>

// ---------------------------------------------------------------------------
// GlobalLocalAwareEncoder — truncated-dependency implementation.
// T1: dilated segments (64/128/256) never cross 256-token boundaries ->
//     output token 0 depends only on tokens [0,256) per batch.
// T2: layer 2 is last -> only token 0 per batch feeds output; layer-2 tail
//     (Q/attn/Wo/LN/FFN/LNf) fused into one 16-CTA kernel.
// Config r contributes to (token t, head h) iff t == h (mod r): attention
// configs write disjoint buffers in parallel; Wo A-load sums with masks.
// ---------------------------------------------------------------------------

#define BATCH   16
#define SEQ     256
#define TOK     (BATCH * SEQ)   // 4096
#define DIM     256
#define HEADS   8
#define HDIM    32
#define FFN_DIM 1024
#define INDIM   512
#define NCTX    4095

__device__ float g_x  [TOK * DIM];
__device__ float g_h  [TOK * DIM];
__device__ float g_q  [TOK * DIM];
__device__ float g_k  [TOK * DIM];
__device__ float g_v  [TOK * DIM];
__device__ float g_acc[TOK * DIM];
__device__ float g_ffn[TOK * FFN_DIM];

__device__ __forceinline__ float gelu_tanh(float x) {
    float x3 = x * x * x;
    return 0.5f * x * (1.0f + tanhf(0.7978845608028654f * (x + 0.044715f * x3)));
}

__device__ __forceinline__ unsigned f2tf32(float f) {
    unsigned u;
    asm("cvt.rna.tf32.f32 %0, %1;" : "=r"(u) : "f"(f));
    return u;
}

__device__ __forceinline__ void mma_tf32(float* d, uint4 a, unsigned b0, unsigned b1) {
    asm volatile(
        "mma.sync.aligned.m16n8k8.row.col.f32.tf32.tf32.f32 "
        "{%0,%1,%2,%3}, {%4,%5,%6,%7}, {%8,%9}, {%0,%1,%2,%3};"
        : "+f"(d[0]), "+f"(d[1]), "+f"(d[2]), "+f"(d[3])
        : "r"(a.x), "r"(a.y), "r"(a.z), "r"(a.w), "r"(b0), "r"(b1));
}

__device__ __forceinline__ float wred_sum(float v) {
#pragma unroll
    for (int o = 16; o > 0; o >>= 1) v += __shfl_xor_sync(0xffffffffu, v, o);
    return v;
}

// positional encoding value for (token row, channel col), dim=256
__device__ __forceinline__ float pe_val(int row, int col,
                                        const float* __restrict__ tpos,
                                        const float* __restrict__ cpos) {
    int b = row >> 8, s = row & 255;
    const float* pp = (s == 0) ? (tpos + (size_t)b * 2)
                               : (cpos + ((size_t)b * NCTX + (s - 1)) * 2);
    float pos = (col < 128) ? pp[0] : pp[1];
    int dd = col & 127;
    int i  = dd & 63;
    float omega = expf(-(float)i * (9.210340371976184f / 64.0f));
    float ang = pos * omega;
    return (dd < 64) ? sinf(ang) : cosf(ang);
}

// ---------------------------------------------------------------------------
// tf32 MMA GEMM. C[4096,N] = A[4096,K] @ B[K,N], B row-major.
// CTA tile 64(M) x BN(N) (BN = 64 or 128), BK=16, double-buffered.
// 256 threads = 8 warps, warp grid 2(M) x 4(N), warp tile 32 x (BN/4).
// EPI: 0 store / 2 gelu(v+bias) / 3 v+res(+bias) / 5 v+bias+0.3*posenc
// ASUM3: A(t,k) = A1 + [t==h mod2]*A2 + [t==h mod4]*A4, h=k>>5.
// blockIdx.z selects (B0,C0)/(B1,C1)/(B2,C2).
// ---------------------------------------------------------------------------
template<int EPI, int BN, bool GATHER, bool ASUM3>
__global__ __launch_bounds__(256)
void mma_gemm(const float* __restrict__ A,
              const float* __restrict__ A2, const float* __restrict__ A4,
              const float* __restrict__ B0, const float* __restrict__ B1,
              const float* __restrict__ B2,
              const float* __restrict__ bias, const float* __restrict__ res,
              float* __restrict__ C0, float* __restrict__ C1, float* __restrict__ C2,
              int N, int K,
              const float* __restrict__ tfeat, const float* __restrict__ cfeat,
              const float* __restrict__ tpos,  const float* __restrict__ cpos)
{
    constexpr int BSST = BN + 8;
    constexpr int NF   = BN / 32;       // n-fragments per warp
    constexpr int NBL  = BN / 16;       // B elements loaded per thread per chunk

    __shared__ unsigned As[2][1024];
    __shared__ unsigned Bs[2][16 * BSST];

    const int z = blockIdx.z;
    const float* B = (z == 0) ? B0 : (z == 1) ? B1 : B2;
    float*       C = (z == 0) ? C0 : (z == 1) ? C1 : C2;

    const int t    = threadIdx.x;
    const int lane = t & 31;
    const int warp = t >> 5;
    const int wm   = warp >> 2;
    const int wn   = warp & 3;
    const int gid  = lane >> 2;
    const int tig  = lane & 3;

    const int bm = blockIdx.y * 64;
    const int bn = blockIdx.x * BN;

    const int a_mf = t >> 6;
    const int al   = t & 31;
    const int arow = a_mf * 16 + (al >> 2);
    const int acol = ((t >> 5) & 1) * 8 + (al & 3);

    const int r0row = bm + arow;
    const int r1row = r0row + 8;

    const float *a1p0, *a1p1;
    const float *a2p0 = nullptr, *a2p1 = nullptr, *a4p0 = nullptr, *a4p1 = nullptr;
    if (GATHER) {
        int b0i = r0row >> 8, s0 = r0row & 255;
        int b1i = r1row >> 8, s1 = r1row & 255;
        a1p0 = (s0 == 0) ? (tfeat + (size_t)b0i * INDIM)
                         : (cfeat + ((size_t)b0i * NCTX + (s0 - 1)) * INDIM);
        a1p1 = (s1 == 0) ? (tfeat + (size_t)b1i * INDIM)
                         : (cfeat + ((size_t)b1i * NCTX + (s1 - 1)) * INDIM);
    } else {
        a1p0 = A + (size_t)r0row * K;
        a1p1 = A + (size_t)r1row * K;
        if (ASUM3) {
            a2p0 = A2 + (size_t)r0row * K;  a2p1 = A2 + (size_t)r1row * K;
            a4p0 = A4 + (size_t)r0row * K;  a4p1 = A4 + (size_t)r1row * K;
        }
    }

    int b_goff[NBL], b_soff[NBL];
#pragma unroll
    for (int i = 0; i < NBL; i++) {
        int idx = t + 256 * i;
        int kk  = idx / BN;
        int n   = idx % BN;
        b_goff[i] = kk * N + bn + n;
        b_soff[i] = kk * BSST + n;
    }

    float accd[2][NF][4];
#pragma unroll
    for (int mf = 0; mf < 2; mf++)
#pragma unroll
        for (int nf = 0; nf < NF; nf++)
#pragma unroll
            for (int r = 0; r < 4; r++) accd[mf][nf][r] = 0.f;

    const int nchunks = K >> 4;
    float pa0, pa1, pa2, pa3;
    float pb[NBL];

    auto loadA = [&](int k0) {
        if (ASUM3) {
            int kc  = k0 + acol;
            int hh  = kc >> 5;      // same head for kc and kc+4 (16-chunk inside 32-block)
            bool m20 = ((r0row ^ hh) & 1) == 0, m40 = ((r0row ^ hh) & 3) == 0;
            bool m21 = ((r1row ^ hh) & 1) == 0, m41 = ((r1row ^ hh) & 3) == 0;
            pa0 = a1p0[kc]     + (m20 ? a2p0[kc]     : 0.f) + (m40 ? a4p0[kc]     : 0.f);
            pa1 = a1p1[kc]     + (m21 ? a2p1[kc]     : 0.f) + (m41 ? a4p1[kc]     : 0.f);
            pa2 = a1p0[kc + 4] + (m20 ? a2p0[kc + 4] : 0.f) + (m40 ? a4p0[kc + 4] : 0.f);
            pa3 = a1p1[kc + 4] + (m21 ? a2p1[kc + 4] : 0.f) + (m41 ? a4p1[kc + 4] : 0.f);
        } else {
            pa0 = a1p0[k0 + acol];     pa1 = a1p1[k0 + acol];
            pa2 = a1p0[k0 + acol + 4]; pa3 = a1p1[k0 + acol + 4];
        }
    };

    {
        loadA(0);
        const float* bp = B;
#pragma unroll
        for (int i = 0; i < NBL; i++) pb[i] = bp[b_goff[i]];
        unsigned* aw = &As[0][t * 4];
        aw[0] = f2tf32(pa0); aw[1] = f2tf32(pa1);
        aw[2] = f2tf32(pa2); aw[3] = f2tf32(pa3);
#pragma unroll
        for (int i = 0; i < NBL; i++) Bs[0][b_soff[i]] = f2tf32(pb[i]);
    }
    __syncthreads();

    for (int c = 0; c < nchunks; c++) {
        const int s = c & 1;
        const bool more = (c + 1 < nchunks);
        if (more) {
            int k0 = (c + 1) << 4;
            loadA(k0);
            const float* bp = B + (size_t)k0 * N;
#pragma unroll
            for (int i = 0; i < NBL; i++) pb[i] = bp[b_goff[i]];
        }

#pragma unroll
        for (int kf = 0; kf < 2; kf++) {
            uint4 afr[2];
            afr[0] = *(const uint4*)&As[s][(((wm * 2 + 0) * 2 + kf) * 32 + lane) * 4];
            afr[1] = *(const uint4*)&As[s][(((wm * 2 + 1) * 2 + kf) * 32 + lane) * 4];
#pragma unroll
            for (int nf = 0; nf < NF; nf++) {
                int cb = wn * (BN / 4) + nf * 8 + gid;
                unsigned bb0 = Bs[s][(kf * 8 + tig) * BSST + cb];
                unsigned bb1 = Bs[s][(kf * 8 + tig + 4) * BSST + cb];
                mma_tf32(accd[0][nf], afr[0], bb0, bb1);
                mma_tf32(accd[1][nf], afr[1], bb0, bb1);
            }
        }

        if (more) {
            const int s2 = s ^ 1;
            unsigned* aw = &As[s2][t * 4];
            aw[0] = f2tf32(pa0); aw[1] = f2tf32(pa1);
            aw[2] = f2tf32(pa2); aw[3] = f2tf32(pa3);
#pragma unroll
            for (int i = 0; i < NBL; i++) Bs[s2][b_soff[i]] = f2tf32(pb[i]);
        }
        __syncthreads();
    }

#pragma unroll
    for (int mf = 0; mf < 2; mf++) {
#pragma unroll
        for (int nf = 0; nf < NF; nf++) {
            int row = bm + wm * 32 + mf * 16 + gid;
            int col = bn + wn * (BN / 4) + nf * 8 + 2 * tig;
#pragma unroll
            for (int half = 0; half < 2; half++) {
                int r = row + half * 8;
                float v0 = accd[mf][nf][half * 2 + 0];
                float v1 = accd[mf][nf][half * 2 + 1];
                size_t idx = (size_t)r * N + col;
                if (EPI == 2) {
                    v0 = gelu_tanh(v0 + bias[col]);
                    v1 = gelu_tanh(v1 + bias[col + 1]);
                } else if (EPI == 3) {
                    if (bias) { v0 += bias[col]; v1 += bias[col + 1]; }
                    v0 += res[idx]; v1 += res[idx + 1];
                } else if (EPI == 5) {
                    v0 += bias[col]     + 0.3f * pe_val(r, col,     tpos, cpos);
                    v1 += bias[col + 1] + 0.3f * pe_val(r, col + 1, tpos, cpos);
                }
                *(float2*)&C[idx] = make_float2(v0, v1);
            }
        }
    }
}

// ---------------------------------------------------------------------------
// LayerNorm: one warp per token, D=256.
// ---------------------------------------------------------------------------
__global__ void ln_kernel(const float* __restrict__ x, const float* __restrict__ sc,
                          const float* __restrict__ bi, float* __restrict__ out,
                          int ntok, int in_stride)
{
    int gw   = (blockIdx.x * blockDim.x + threadIdx.x) >> 5;
    int lane = threadIdx.x & 31;
    if (gw >= ntok) return;
    const float* xp = x + (size_t)gw * in_stride;
    float4 v0 = *(const float4*)&xp[lane * 4];
    float4 v1 = *(const float4*)&xp[128 + lane * 4];
    float va[8] = {v0.x, v0.y, v0.z, v0.w, v1.x, v1.y, v1.z, v1.w};

    float s = 0.f;
#pragma unroll
    for (int c = 0; c < 8; c++) s += va[c];
    s = wred_sum(s);
    float mu = s * (1.0f / 256.0f);

    float ss = 0.f;
#pragma unroll
    for (int c = 0; c < 8; c++) { float d = va[c] - mu; ss += d * d; }
    ss = wred_sum(ss);
    float inv = rsqrtf(ss * (1.0f / 256.0f) + 1e-5f);

    float ovals[8];
#pragma unroll
    for (int c = 0; c < 8; c++) {
        int d = (c < 4) ? (lane * 4 + c) : (128 + lane * 4 + (c - 4));
        ovals[c] = (va[c] - mu) * inv * sc[d] + bi[d];
    }
    float* op = out + (size_t)gw * 256;
    *(float4*)&op[lane * 4]       = make_float4(ovals[0], ovals[1], ovals[2], ovals[3]);
    *(float4*)&op[128 + lane * 4] = make_float4(ovals[4], ovals[5], ovals[6], ovals[7]);
}

// ---------------------------------------------------------------------------
// Layer-1 dilated attention, all 3 configs in ONE launch (grid 896).
// bid<512: (w=64,r=1)->b1; <768: (w=128,r=2)->b2; else (w=256,r=4)->b4.
// Each config writes its own buffer (no RMW chain). V read from global (L2).
// ---------------------------------------------------------------------------
__global__ __launch_bounds__(256)
void attn_all_kernel(const float* __restrict__ q, const float* __restrict__ k,
                     const float* __restrict__ v,
                     float* __restrict__ b1, float* __restrict__ b2,
                     float* __restrict__ b4)
{
    __shared__ float qs[64 * 36];
    __shared__ float ks[64 * 36];
    __shared__ float smP[64 * 65];

    int bid = blockIdx.x;
    int w, r;
    float* buf;
    if (bid < 512)      { w = 64;  r = 1; buf = b1; }
    else if (bid < 768) { bid -= 512; w = 128; r = 2; buf = b2; }
    else                { bid -= 768; w = 256; r = 4; buf = b4; }

    const int nseg = SEQ / w;
    const int h   = bid & 7;
    const int seg = (bid >> 3) % nseg;
    const int b   = bid / (8 * nseg);
    const int base = b * SEQ + seg * w;
    const int off  = h % r;
    const int t = threadIdx.x;

#pragma unroll
    for (int i = 0; i < 2; i++) {
        int idx = t + 256 * i;          // 0..511
        int j  = idx >> 3;
        int dq = (idx & 7) * 4;
        int tok = base + off + r * j;
        size_t gi = (size_t)tok * DIM + h * HDIM + dq;
        *(float4*)&qs[j * 36 + dq] = *(const float4*)&q[gi];
        *(float4*)&ks[j * 36 + dq] = *(const float4*)&k[gi];
    }
    __syncthreads();

    // QK + softmax: thread = (rp = t>>3 rows {rp,rp+32}, jo = t&7 keys jo+8*jj)
    {
        const int rp = t >> 3;
        const int jo = t & 7;
        float4 qa[8], qb[8];
#pragma unroll
        for (int u = 0; u < 8; u++) {
            qa[u] = *(const float4*)&qs[rp * 36 + u * 4];
            qb[u] = *(const float4*)&qs[(rp + 32) * 36 + u * 4];
        }
        float s0[8], s1[8];
#pragma unroll
        for (int jj = 0; jj < 8; jj++) {
            int j = jo + 8 * jj;
            float d0 = 0.f, d1 = 0.f;
#pragma unroll
            for (int u = 0; u < 8; u++) {
                float4 kv = *(const float4*)&ks[j * 36 + u * 4];
                d0 += qa[u].x * kv.x + qa[u].y * kv.y + qa[u].z * kv.z + qa[u].w * kv.w;
                d1 += qb[u].x * kv.x + qb[u].y * kv.y + qb[u].z * kv.z + qb[u].w * kv.w;
            }
            s0[jj] = d0 * 0.17677669529663687f;
            s1[jj] = d1 * 0.17677669529663687f;
        }

        float m0 = s0[0], m1 = s1[0];
#pragma unroll
        for (int jj = 1; jj < 8; jj++) { m0 = fmaxf(m0, s0[jj]); m1 = fmaxf(m1, s1[jj]); }
#pragma unroll
        for (int o = 4; o > 0; o >>= 1) {
            m0 = fmaxf(m0, __shfl_xor_sync(0xffffffffu, m0, o));
            m1 = fmaxf(m1, __shfl_xor_sync(0xffffffffu, m1, o));
        }
        float su0 = 0.f, su1 = 0.f;
#pragma unroll
        for (int jj = 0; jj < 8; jj++) {
            s0[jj] = __expf(s0[jj] - m0); su0 += s0[jj];
            s1[jj] = __expf(s1[jj] - m1); su1 += s1[jj];
        }
#pragma unroll
        for (int o = 4; o > 0; o >>= 1) {
            su0 += __shfl_xor_sync(0xffffffffu, su0, o);
            su1 += __shfl_xor_sync(0xffffffffu, su1, o);
        }
        float i0 = 1.0f / su0, i1 = 1.0f / su1;
#pragma unroll
        for (int jj = 0; jj < 8; jj++) {
            int j = jo + 8 * jj;
            smP[rp * 65 + j]        = s0[jj] * i0;
            smP[(rp + 32) * 65 + j] = s1[jj] * i1;
        }
    }
    __syncthreads();

    // PV: thread = (row = t>>2, dg = (t&3)*8); V from global (L2-resident)
    {
        const int row = t >> 2;
        const int dg  = (t & 3) * 8;
        const float* vbase = v + (size_t)(base + off) * DIM + h * HDIM + dg;
        const size_t vstep = (size_t)r * DIM;
        float4 o0 = make_float4(0.f, 0.f, 0.f, 0.f);
        float4 o1 = make_float4(0.f, 0.f, 0.f, 0.f);
#pragma unroll 8
        for (int j = 0; j < 64; j++) {
            float p = smP[row * 65 + j];
            const float4* vp = (const float4*)(vbase + (size_t)j * vstep);
            float4 va = vp[0];
            float4 vb = vp[1];
            o0.x += p * va.x; o0.y += p * va.y; o0.z += p * va.z; o0.w += p * va.w;
            o1.x += p * vb.x; o1.y += p * vb.y; o1.z += p * vb.z; o1.w += p * vb.w;
        }
        const float third = 1.0f / 3.0f;
        int tok = base + off + r * row;
        float* ap = &buf[(size_t)tok * DIM + h * HDIM + dg];
        *(float4*)&ap[0] = make_float4(o0.x * third, o0.y * third, o0.z * third, o0.w * third);
        *(float4*)&ap[4] = make_float4(o1.x * third, o1.y * third, o1.z * third, o1.w * third);
    }
}

// ---------------------------------------------------------------------------
// Layer-2 fused tail: per batch (16 CTAs, 256 threads):
//   q = h0 @ Wq;  att = dilated-attn(token0);  x1 = att @ Wo + x0;
//   h2 = LN2(x1); f = gelu(h2 @ W1 + b1); y = f @ W2 + b2 + x1; out = LNf(y)
// h0 = LN1(x) row (from g_h), x0 = residual row (from g_x).
// ---------------------------------------------------------------------------
__global__ __launch_bounds__(256)
void tail_kernel(const float* __restrict__ x,  const float* __restrict__ hh,
                 const float* __restrict__ k,  const float* __restrict__ v,
                 const float* __restrict__ Wq, const float* __restrict__ Wo,
                 const float* __restrict__ W1, const float* __restrict__ W2,
                 const float* __restrict__ b1v, const float* __restrict__ b2v,
                 const float* __restrict__ ln2s, const float* __restrict__ ln2b,
                 const float* __restrict__ lnfs, const float* __restrict__ lnfb,
                 float* __restrict__ out)
{
    __shared__ float xs[256], hq[256], qsh[256], att[256], x1[256], h2[256];
    __shared__ float f[1024];
    __shared__ float red[4 * 256];
    __shared__ float psh[8][64];
    __shared__ float rsum[8];

    const int b    = blockIdx.x;
    const int t    = threadIdx.x;
    const int lane = t & 31;
    const int wrp  = t >> 5;
    const size_t row0 = (size_t)b * SEQ * DIM;

    xs[t] = x[row0 + t];
    hq[t] = hh[row0 + t];
    __syncthreads();

    // ---- q = hq @ Wq (split-K x4) ----
    {
        const int c4 = (t & 63) * 4;
        const int ks = t >> 6;
        float4 a = make_float4(0.f, 0.f, 0.f, 0.f);
        for (int kk = 0; kk < 64; kk++) {
            int ki = ks * 64 + kk;
            float s = hq[ki];
            float4 w = *(const float4*)&Wq[(size_t)ki * 256 + c4];
            a.x += s * w.x; a.y += s * w.y; a.z += s * w.z; a.w += s * w.w;
        }
        *(float4*)&red[ks * 256 + c4] = a;
        __syncthreads();
        qsh[t] = red[t] + red[256 + t] + red[512 + t] + red[768 + t];
        __syncthreads();
    }

    // ---- token-0 dilated attention; head h contributes from r iff h%r==0 ----
    {
        const int h = wrp;
        float o = 0.f;
        const float4* qv = (const float4*)&qsh[h * 32];
#pragma unroll
        for (int c = 0; c < 3; c++) {
            const int r = 1 << c;
            if (h % r == 0) {
                const float4* k0p = (const float4*)(k + ((size_t)(b * 256 + r * lane) * DIM) + h * 32);
                const float4* k1p = (const float4*)(k + ((size_t)(b * 256 + r * (lane + 32)) * DIM) + h * 32);
                float s0 = 0.f, s1 = 0.f;
#pragma unroll
                for (int u = 0; u < 8; u++) {
                    float4 qd = qv[u];
                    float4 ka = k0p[u];
                    float4 kb = k1p[u];
                    s0 += qd.x * ka.x + qd.y * ka.y + qd.z * ka.z + qd.w * ka.w;
                    s1 += qd.x * kb.x + qd.y * kb.y + qd.z * kb.z + qd.w * kb.w;
                }
                s0 *= 0.17677669529663687f;
                s1 *= 0.17677669529663687f;
                float mx = fmaxf(s0, s1);
#pragma unroll
                for (int ofs = 16; ofs > 0; ofs >>= 1)
                    mx = fmaxf(mx, __shfl_xor_sync(0xffffffffu, mx, ofs));
                float e0 = __expf(s0 - mx), e1 = __expf(s1 - mx);
                float sm = wred_sum(e0 + e1);
                float inv = 1.0f / sm;
                psh[h][lane]      = e0 * inv;
                psh[h][lane + 32] = e1 * inv;
                __syncwarp();
                float oc = 0.f;
#pragma unroll 8
                for (int j = 0; j < 64; j++)
                    oc += psh[h][j] * v[((size_t)(b * 256 + r * j) * DIM) + h * 32 + lane];
                o += oc;
                __syncwarp();
            }
        }
        att[h * 32 + lane] = o * (1.0f / 3.0f);
    }
    __syncthreads();

    // ---- x1 = att @ Wo + xs ----
    {
        const int c4 = (t & 63) * 4;
        const int ks = t >> 6;
        float4 a = make_float4(0.f, 0.f, 0.f, 0.f);
        for (int kk = 0; kk < 64; kk++) {
            int ki = ks * 64 + kk;
            float s = att[ki];
            float4 w = *(const float4*)&Wo[(size_t)ki * 256 + c4];
            a.x += s * w.x; a.y += s * w.y; a.z += s * w.z; a.w += s * w.w;
        }
        __syncthreads();   // red free
        *(float4*)&red[ks * 256 + c4] = a;
        __syncthreads();
        x1[t] = red[t] + red[256 + t] + red[512 + t] + red[768 + t] + xs[t];
        __syncthreads();
    }

    // ---- h2 = LN2(x1) ----
    {
        float val = x1[t];
        float s = wred_sum(val);
        if (lane == 0) rsum[wrp] = s;
        __syncthreads();
        float tot = 0.f;
#pragma unroll
        for (int i = 0; i < 8; i++) tot += rsum[i];
        float mu = tot * (1.0f / 256.0f);
        __syncthreads();
        float dv = val - mu;
        float s2 = wred_sum(dv * dv);
        if (lane == 0) rsum[wrp] = s2;
        __syncthreads();
        float tv = 0.f;
#pragma unroll
        for (int i = 0; i < 8; i++) tv += rsum[i];
        float inv = rsqrtf(tv * (1.0f / 256.0f) + 1e-5f);
        h2[t] = dv * inv * ln2s[t] + ln2b[t];
        __syncthreads();
    }

    // ---- f = gelu(h2 @ W1 + b1) : 1024 cols, 4 per thread ----
    {
        const int c4 = t * 4;
        float4 a = make_float4(0.f, 0.f, 0.f, 0.f);
        for (int ki = 0; ki < 256; ki++) {
            float s = h2[ki];
            float4 w = *(const float4*)&W1[(size_t)ki * 1024 + c4];
            a.x += s * w.x; a.y += s * w.y; a.z += s * w.z; a.w += s * w.w;
        }
        float4 bb = *(const float4*)&b1v[c4];
        f[c4 + 0] = gelu_tanh(a.x + bb.x);
        f[c4 + 1] = gelu_tanh(a.y + bb.y);
        f[c4 + 2] = gelu_tanh(a.z + bb.z);
        f[c4 + 3] = gelu_tanh(a.w + bb.w);
        __syncthreads();
    }

    // ---- y = f @ W2 + b2 + x1 ; out = LNf(y) ----
    {
        const int c4 = (t & 63) * 4;
        const int ks = t >> 6;
        float4 a = make_float4(0.f, 0.f, 0.f, 0.f);
        for (int kk = 0; kk < 256; kk++) {
            int ki = ks * 256 + kk;
            float s = f[ki];
            float4 w = *(const float4*)&W2[(size_t)ki * 256 + c4];
            a.x += s * w.x; a.y += s * w.y; a.z += s * w.z; a.w += s * w.w;
        }
        *(float4*)&red[ks * 256 + c4] = a;
        __syncthreads();
        float y = red[t] + red[256 + t] + red[512 + t] + red[768 + t] + b2v[t] + x1[t];

        float s = wred_sum(y);
        if (lane == 0) rsum[wrp] = s;
        __syncthreads();
        float tot = 0.f;
#pragma unroll
        for (int i = 0; i < 8; i++) tot += rsum[i];
        float mu = tot * (1.0f / 256.0f);
        __syncthreads();
        float dv = y - mu;
        float s2 = wred_sum(dv * dv);
        if (lane == 0) rsum[wrp] = s2;
        __syncthreads();
        float tv = 0.f;
#pragma unroll
        for (int i = 0; i < 8; i++) tv += rsum[i];
        float inv = rsqrtf(tv * (1.0f / 256.0f) + 1e-5f);
        out[(size_t)b * 256 + t] = dv * inv * lnfs[t] + lnfb[t];
    }
}

// ---------------------------------------------------------------------------
// Orchestration
// ---------------------------------------------------------------------------
extern "C" void kernel_launch(void* const* d_in, const int* in_sizes, int n_in,
                              void* d_out, int out_size)
{
    const float* target_feat   = (const float*)d_in[0];
    const float* context_feats = (const float*)d_in[1];
    const float* target_pos    = (const float*)d_in[2];
    const float* context_pos   = (const float*)d_in[3];
    const float* W_proj        = (const float*)d_in[4];
    const float* b_proj        = (const float*)d_in[5];
    const float* Wq            = (const float*)d_in[6];
    const float* Wk            = (const float*)d_in[7];
    const float* Wv            = (const float*)d_in[8];
    const float* Wo            = (const float*)d_in[9];
    const float* ln1_s         = (const float*)d_in[10];
    const float* ln1_b         = (const float*)d_in[11];
    const float* ln2_s         = (const float*)d_in[12];
    const float* ln2_b         = (const float*)d_in[13];
    const float* W1            = (const float*)d_in[14];
    const float* b1            = (const float*)d_in[15];
    const float* W2            = (const float*)d_in[16];
    const float* b2            = (const float*)d_in[17];
    const float* lnf_s         = (const float*)d_in[18];
    const float* lnf_b         = (const float*)d_in[19];
    float* out = (float*)d_out;

    float *x, *h, *q, *k, *v, *accb, *ffn;
    cudaGetSymbolAddress((void**)&x,    g_x);
    cudaGetSymbolAddress((void**)&h,    g_h);
    cudaGetSymbolAddress((void**)&q,    g_q);
    cudaGetSymbolAddress((void**)&k,    g_k);
    cudaGetSymbolAddress((void**)&v,    g_v);
    cudaGetSymbolAddress((void**)&accb, g_acc);
    cudaGetSymbolAddress((void**)&ffn,  g_ffn);

    const dim3 blk(256);
    const dim3 gN64 (DIM / 64, TOK / 64, 1);        // (4, 64)
    const dim3 gQKV (DIM / 64, TOK / 64, 3);        // (4, 64, 3)
    const dim3 gKV  (DIM / 64, TOK / 64, 2);        // (4, 64, 2)
    const dim3 gFFN1(FFN_DIM / 128, TOK / 64, 1);   // (8, 64)

    // 1. Projection (+bias +posenc fused), K=512
    mma_gemm<5, 64, true, false><<<gN64, blk>>>(
        nullptr, nullptr, nullptr, W_proj, nullptr, nullptr,
        b_proj, nullptr, x, nullptr, nullptr, DIM, INDIM,
        target_feat, context_feats, target_pos, context_pos);

    // ======================= Layer 1 (full) =======================
    // 2. LN1 -> h
    ln_kernel<<<(TOK * 32) / 256, 256>>>(x, ln1_s, ln1_b, h, TOK, DIM);

    // 3. QKV fused
    mma_gemm<0, 64, false, false><<<gQKV, blk>>>(
        h, nullptr, nullptr, Wq, Wk, Wv,
        nullptr, nullptr, q, k, v, DIM, DIM,
        nullptr, nullptr, nullptr, nullptr);

    // 4. Attention, all configs in one launch -> buffers acc/h/ffn
    attn_all_kernel<<<896, blk>>>(q, k, v, accb, h, ffn);

    // 5. Wo with masked 3-buffer A-sum + residual
    mma_gemm<3, 64, false, true><<<gN64, blk>>>(
        accb, h, ffn, Wo, nullptr, nullptr,
        nullptr, x, x, nullptr, nullptr, DIM, DIM,
        nullptr, nullptr, nullptr, nullptr);

    // 6. LN2 -> h
    ln_kernel<<<(TOK * 32) / 256, 256>>>(x, ln2_s, ln2_b, h, TOK, DIM);

    // 7. FFN1: ffn = gelu(h @ W1 + b1)
    mma_gemm<2, 128, false, false><<<gFFN1, blk>>>(
        h, nullptr, nullptr, W1, nullptr, nullptr,
        b1, nullptr, ffn, nullptr, nullptr, FFN_DIM, DIM,
        nullptr, nullptr, nullptr, nullptr);

    // 8. FFN2: x = ffn @ W2 + b2 + x
    mma_gemm<3, 64, false, false><<<gN64, blk>>>(
        ffn, nullptr, nullptr, W2, nullptr, nullptr,
        b2, x, x, nullptr, nullptr, DIM, FFN_DIM,
        nullptr, nullptr, nullptr, nullptr);

    // ================== Layer 2 (token-0 truncated) ==================
    // 9. LN1(l2) full -> h (K,V need all tokens)
    ln_kernel<<<(TOK * 32) / 256, 256>>>(x, ln1_s + DIM, ln1_b + DIM, h, TOK, DIM);

    // 10. K,V full (fused z=2)
    mma_gemm<0, 64, false, false><<<gKV, blk>>>(
        h, nullptr, nullptr, Wk + DIM * DIM, Wv + DIM * DIM, nullptr,
        nullptr, nullptr, k, v, nullptr, DIM, DIM,
        nullptr, nullptr, nullptr, nullptr);

    // 11. Fused tail: q gemv, attn, Wo+res, LN2, FFN, LNf -> out
    tail_kernel<<<BATCH, blk>>>(
        x, h, k, v,
        Wq + DIM * DIM, Wo + DIM * DIM,
        W1 + DIM * FFN_DIM, W2 + FFN_DIM * DIM,
        b1 + FFN_DIM, b2 + DIM,
        ln2_s + DIM, ln2_b + DIM, lnf_s, lnf_b, out);
}

// round 6
// speedup vs baseline: 3.0076x; 1.0933x over previous
#include <cuda_runtime.h>
#include <math.h>

// ---------------------------------------------------------------------------
// GlobalLocalAwareEncoder — truncated-dependency implementation.
// T1: dilated segments (64/128/256) never cross 256-token boundaries ->
//     output token 0 depends only on tokens [0,256) per batch.
// T2: layer 2 is last -> only token 0 per batch feeds output; layer-2 tail
//     fused into one 16-CTA kernel.
// Attention configs write disjoint buffers (t==h mod r); Wo sums with masks.
// Attention runs on tf32 m16n8k8 tensor cores (128-thread CTAs: 4 warps x
// 16 rows = 64 rows — fixes the R5 OOB where 8 warps addressed 128 rows).
// ---------------------------------------------------------------------------

#define BATCH   16
#define SEQ     256
#define TOK     (BATCH * SEQ)   // 4096
#define DIM     256
#define HEADS   8
#define HDIM    32
#define FFN_DIM 1024
#define INDIM   512
#define NCTX    4095

__device__ float g_x  [TOK * DIM];
__device__ float g_h  [TOK * DIM];
__device__ float g_q  [TOK * DIM];
__device__ float g_k  [TOK * DIM];
__device__ float g_v  [TOK * DIM];
__device__ float g_acc[TOK * DIM];
__device__ float g_ffn[TOK * FFN_DIM];

__device__ __forceinline__ float gelu_tanh(float x) {
    float x3 = x * x * x;
    return 0.5f * x * (1.0f + tanhf(0.7978845608028654f * (x + 0.044715f * x3)));
}

__device__ __forceinline__ unsigned f2tf32(float f) {
    unsigned u;
    asm("cvt.rna.tf32.f32 %0, %1;" : "=r"(u) : "f"(f));
    return u;
}

__device__ __forceinline__ void mma_tf32(float* d, uint4 a, unsigned b0, unsigned b1) {
    asm volatile(
        "mma.sync.aligned.m16n8k8.row.col.f32.tf32.tf32.f32 "
        "{%0,%1,%2,%3}, {%4,%5,%6,%7}, {%8,%9}, {%0,%1,%2,%3};"
        : "+f"(d[0]), "+f"(d[1]), "+f"(d[2]), "+f"(d[3])
        : "r"(a.x), "r"(a.y), "r"(a.z), "r"(a.w), "r"(b0), "r"(b1));
}

__device__ __forceinline__ float wred_sum(float v) {
#pragma unroll
    for (int o = 16; o > 0; o >>= 1) v += __shfl_xor_sync(0xffffffffu, v, o);
    return v;
}

// positional encoding value for (token row, channel col), dim=256
__device__ __forceinline__ float pe_val(int row, int col,
                                        const float* __restrict__ tpos,
                                        const float* __restrict__ cpos) {
    int b = row >> 8, s = row & 255;
    const float* pp = (s == 0) ? (tpos + (size_t)b * 2)
                               : (cpos + ((size_t)b * NCTX + (s - 1)) * 2);
    float pos = (col < 128) ? pp[0] : pp[1];
    int dd = col & 127;
    int i  = dd & 63;
    float omega = expf(-(float)i * (9.210340371976184f / 64.0f));
    float ang = pos * omega;
    return (dd < 64) ? sinf(ang) : cosf(ang);
}

// ---------------------------------------------------------------------------
// tf32 MMA GEMM. C[4096,N] = A[4096,K] @ B[K,N], B row-major.
// CTA tile 64(M) x BN(N), BK=16, double-buffered. 8 warps, warp 32 x (BN/4).
// EPI: 0 store / 2 gelu(v+bias) / 3 v+res(+bias) / 5 v+bias+0.3*posenc
// ASUM3: A(t,k) = A1 + [t==h mod2]*A2 + [t==h mod4]*A4, h=k>>5.
// ---------------------------------------------------------------------------
template<int EPI, int BN, bool GATHER, bool ASUM3>
__global__ __launch_bounds__(256)
void mma_gemm(const float* __restrict__ A,
              const float* __restrict__ A2, const float* __restrict__ A4,
              const float* __restrict__ B0, const float* __restrict__ B1,
              const float* __restrict__ B2,
              const float* __restrict__ bias, const float* __restrict__ res,
              float* __restrict__ C0, float* __restrict__ C1, float* __restrict__ C2,
              int N, int K,
              const float* __restrict__ tfeat, const float* __restrict__ cfeat,
              const float* __restrict__ tpos,  const float* __restrict__ cpos)
{
    constexpr int BSST = BN + 8;
    constexpr int NF   = BN / 32;
    constexpr int NBL  = BN / 16;

    __shared__ unsigned As[2][1024];
    __shared__ unsigned Bs[2][16 * BSST];

    const int z = blockIdx.z;
    const float* B = (z == 0) ? B0 : (z == 1) ? B1 : B2;
    float*       C = (z == 0) ? C0 : (z == 1) ? C1 : C2;

    const int t    = threadIdx.x;
    const int lane = t & 31;
    const int warp = t >> 5;
    const int wm   = warp >> 2;
    const int wn   = warp & 3;
    const int gid  = lane >> 2;
    const int tig  = lane & 3;

    const int bm = blockIdx.y * 64;
    const int bn = blockIdx.x * BN;

    const int a_mf = t >> 6;
    const int al   = t & 31;
    const int arow = a_mf * 16 + (al >> 2);
    const int acol = ((t >> 5) & 1) * 8 + (al & 3);

    const int r0row = bm + arow;
    const int r1row = r0row + 8;

    const float *a1p0, *a1p1;
    const float *a2p0 = nullptr, *a2p1 = nullptr, *a4p0 = nullptr, *a4p1 = nullptr;
    if (GATHER) {
        int b0i = r0row >> 8, s0 = r0row & 255;
        int b1i = r1row >> 8, s1 = r1row & 255;
        a1p0 = (s0 == 0) ? (tfeat + (size_t)b0i * INDIM)
                         : (cfeat + ((size_t)b0i * NCTX + (s0 - 1)) * INDIM);
        a1p1 = (s1 == 0) ? (tfeat + (size_t)b1i * INDIM)
                         : (cfeat + ((size_t)b1i * NCTX + (s1 - 1)) * INDIM);
    } else {
        a1p0 = A + (size_t)r0row * K;
        a1p1 = A + (size_t)r1row * K;
        if (ASUM3) {
            a2p0 = A2 + (size_t)r0row * K;  a2p1 = A2 + (size_t)r1row * K;
            a4p0 = A4 + (size_t)r0row * K;  a4p1 = A4 + (size_t)r1row * K;
        }
    }

    int b_goff[NBL], b_soff[NBL];
#pragma unroll
    for (int i = 0; i < NBL; i++) {
        int idx = t + 256 * i;
        int kk  = idx / BN;
        int n   = idx % BN;
        b_goff[i] = kk * N + bn + n;
        b_soff[i] = kk * BSST + n;
    }

    float accd[2][NF][4];
#pragma unroll
    for (int mf = 0; mf < 2; mf++)
#pragma unroll
        for (int nf = 0; nf < NF; nf++)
#pragma unroll
            for (int r = 0; r < 4; r++) accd[mf][nf][r] = 0.f;

    const int nchunks = K >> 4;
    float pa0, pa1, pa2, pa3;
    float pb[NBL];

    auto loadA = [&](int k0) {
        if (ASUM3) {
            int kc  = k0 + acol;
            int hh  = kc >> 5;
            bool m20 = ((r0row ^ hh) & 1) == 0, m40 = ((r0row ^ hh) & 3) == 0;
            bool m21 = ((r1row ^ hh) & 1) == 0, m41 = ((r1row ^ hh) & 3) == 0;
            pa0 = a1p0[kc]     + (m20 ? a2p0[kc]     : 0.f) + (m40 ? a4p0[kc]     : 0.f);
            pa1 = a1p1[kc]     + (m21 ? a2p1[kc]     : 0.f) + (m41 ? a4p1[kc]     : 0.f);
            pa2 = a1p0[kc + 4] + (m20 ? a2p0[kc + 4] : 0.f) + (m40 ? a4p0[kc + 4] : 0.f);
            pa3 = a1p1[kc + 4] + (m21 ? a2p1[kc + 4] : 0.f) + (m41 ? a4p1[kc + 4] : 0.f);
        } else {
            pa0 = a1p0[k0 + acol];     pa1 = a1p1[k0 + acol];
            pa2 = a1p0[k0 + acol + 4]; pa3 = a1p1[k0 + acol + 4];
        }
    };

    {
        loadA(0);
        const float* bp = B;
#pragma unroll
        for (int i = 0; i < NBL; i++) pb[i] = bp[b_goff[i]];
        unsigned* aw = &As[0][t * 4];
        aw[0] = f2tf32(pa0); aw[1] = f2tf32(pa1);
        aw[2] = f2tf32(pa2); aw[3] = f2tf32(pa3);
#pragma unroll
        for (int i = 0; i < NBL; i++) Bs[0][b_soff[i]] = f2tf32(pb[i]);
    }
    __syncthreads();

    for (int c = 0; c < nchunks; c++) {
        const int s = c & 1;
        const bool more = (c + 1 < nchunks);
        if (more) {
            int k0 = (c + 1) << 4;
            loadA(k0);
            const float* bp = B + (size_t)k0 * N;
#pragma unroll
            for (int i = 0; i < NBL; i++) pb[i] = bp[b_goff[i]];
        }

#pragma unroll
        for (int kf = 0; kf < 2; kf++) {
            uint4 afr[2];
            afr[0] = *(const uint4*)&As[s][(((wm * 2 + 0) * 2 + kf) * 32 + lane) * 4];
            afr[1] = *(const uint4*)&As[s][(((wm * 2 + 1) * 2 + kf) * 32 + lane) * 4];
#pragma unroll
            for (int nf = 0; nf < NF; nf++) {
                int cb = wn * (BN / 4) + nf * 8 + gid;
                unsigned bb0 = Bs[s][(kf * 8 + tig) * BSST + cb];
                unsigned bb1 = Bs[s][(kf * 8 + tig + 4) * BSST + cb];
                mma_tf32(accd[0][nf], afr[0], bb0, bb1);
                mma_tf32(accd[1][nf], afr[1], bb0, bb1);
            }
        }

        if (more) {
            const int s2 = s ^ 1;
            unsigned* aw = &As[s2][t * 4];
            aw[0] = f2tf32(pa0); aw[1] = f2tf32(pa1);
            aw[2] = f2tf32(pa2); aw[3] = f2tf32(pa3);
#pragma unroll
            for (int i = 0; i < NBL; i++) Bs[s2][b_soff[i]] = f2tf32(pb[i]);
        }
        __syncthreads();
    }

#pragma unroll
    for (int mf = 0; mf < 2; mf++) {
#pragma unroll
        for (int nf = 0; nf < NF; nf++) {
            int row = bm + wm * 32 + mf * 16 + gid;
            int col = bn + wn * (BN / 4) + nf * 8 + 2 * tig;
#pragma unroll
            for (int half = 0; half < 2; half++) {
                int r = row + half * 8;
                float v0 = accd[mf][nf][half * 2 + 0];
                float v1 = accd[mf][nf][half * 2 + 1];
                size_t idx = (size_t)r * N + col;
                if (EPI == 2) {
                    v0 = gelu_tanh(v0 + bias[col]);
                    v1 = gelu_tanh(v1 + bias[col + 1]);
                } else if (EPI == 3) {
                    if (bias) { v0 += bias[col]; v1 += bias[col + 1]; }
                    v0 += res[idx]; v1 += res[idx + 1];
                } else if (EPI == 5) {
                    v0 += bias[col]     + 0.3f * pe_val(r, col,     tpos, cpos);
                    v1 += bias[col + 1] + 0.3f * pe_val(r, col + 1, tpos, cpos);
                }
                *(float2*)&C[idx] = make_float2(v0, v1);
            }
        }
    }
}

// ---------------------------------------------------------------------------
// LayerNorm: one warp per token, D=256.
// ---------------------------------------------------------------------------
__global__ void ln_kernel(const float* __restrict__ x, const float* __restrict__ sc,
                          const float* __restrict__ bi, float* __restrict__ out,
                          int ntok, int in_stride)
{
    int gw   = (blockIdx.x * blockDim.x + threadIdx.x) >> 5;
    int lane = threadIdx.x & 31;
    if (gw >= ntok) return;
    const float* xp = x + (size_t)gw * in_stride;
    float4 v0 = *(const float4*)&xp[lane * 4];
    float4 v1 = *(const float4*)&xp[128 + lane * 4];
    float va[8] = {v0.x, v0.y, v0.z, v0.w, v1.x, v1.y, v1.z, v1.w};

    float s = 0.f;
#pragma unroll
    for (int c = 0; c < 8; c++) s += va[c];
    s = wred_sum(s);
    float mu = s * (1.0f / 256.0f);

    float ss = 0.f;
#pragma unroll
    for (int c = 0; c < 8; c++) { float d = va[c] - mu; ss += d * d; }
    ss = wred_sum(ss);
    float inv = rsqrtf(ss * (1.0f / 256.0f) + 1e-5f);

    float ovals[8];
#pragma unroll
    for (int c = 0; c < 8; c++) {
        int d = (c < 4) ? (lane * 4 + c) : (128 + lane * 4 + (c - 4));
        ovals[c] = (va[c] - mu) * inv * sc[d] + bi[d];
    }
    float* op = out + (size_t)gw * 256;
    *(float4*)&op[lane * 4]       = make_float4(ovals[0], ovals[1], ovals[2], ovals[3]);
    *(float4*)&op[128 + lane * 4] = make_float4(ovals[4], ovals[5], ovals[6], ovals[7]);
}

// ---------------------------------------------------------------------------
// Layer-1 dilated attention on tf32 tensor cores. One launch, grid 896,
// 128 threads (4 warps; warp w owns rows 16w..16w+15 — 64 rows total).
// bid<512: (w=64,r=1)->b1; <768: (w=128,r=2)->b2; else (w=256,r=4)->b4.
// S = Q(64x32) K^T -> softmax in regs -> O = P(64x64) V(64x32).
// smem strides: Q/K 36, V 40, P 68. smP overlays Q/K after the QK phase.
// ---------------------------------------------------------------------------
__global__ __launch_bounds__(128)
void attn_all_kernel(const float* __restrict__ q, const float* __restrict__ k,
                     const float* __restrict__ v,
                     float* __restrict__ b1, float* __restrict__ b2,
                     float* __restrict__ b4)
{
    __shared__ unsigned sh[64 * 36 * 2 + 64 * 40];   // 7168 words = 28KB
    unsigned* qs  = sh;                 // [64][36]
    unsigned* ks  = sh + 64 * 36;       // [64][36]
    unsigned* vs  = sh + 64 * 72;       // [64][40]
    unsigned* smP = sh;                 // [64][68] overlays qs+ks (4352 <= 4608)

    int bid = blockIdx.x;
    int r, w;
    float* buf;
    if (bid < 512)      { w = 64;  r = 1; buf = b1; }
    else if (bid < 768) { bid -= 512; w = 128; r = 2; buf = b2; }
    else                { bid -= 768; w = 256; r = 4; buf = b4; }

    const int nseg = SEQ / w;
    const int h   = bid & 7;
    const int seg = (bid >> 3) % nseg;
    const int b   = bid / (8 * nseg);
    const int base = b * SEQ + seg * w;
    const int off  = h % r;
    const int t    = threadIdx.x;
    const int lane = t & 31;
    const int wrp  = t >> 5;             // 0..3
    const int gid  = lane >> 2;          // 0..7
    const int tig  = lane & 3;           // 0..3

    // ---- fill Q,K,V (tf32-converted): 512 float4 per array, 128 threads ----
#pragma unroll
    for (int i = 0; i < 4; i++) {
        int idx = t + 128 * i;          // 0..511
        int j  = idx >> 3;
        int dq = (idx & 7) * 4;
        int tok = base + off + r * j;
        size_t gi = (size_t)tok * DIM + h * HDIM + dq;
        float4 qv = *(const float4*)&q[gi];
        float4 kv = *(const float4*)&k[gi];
        float4 vv = *(const float4*)&v[gi];
        uint4 qu = make_uint4(f2tf32(qv.x), f2tf32(qv.y), f2tf32(qv.z), f2tf32(qv.w));
        uint4 ku = make_uint4(f2tf32(kv.x), f2tf32(kv.y), f2tf32(kv.z), f2tf32(kv.w));
        uint4 vu = make_uint4(f2tf32(vv.x), f2tf32(vv.y), f2tf32(vv.z), f2tf32(vv.w));
        *(uint4*)&qs[j * 36 + dq] = qu;
        *(uint4*)&ks[j * 36 + dq] = ku;
        *(uint4*)&vs[j * 40 + dq] = vu;
    }
    __syncthreads();

    // ---- QK: S[16 rows x 64 cols] per warp, k=32 (4 steps) ----
    const int rA = wrp * 16 + gid;       // 0..55
    const int rB = rA + 8;               // 8..63
    float sacc[8][4];
#pragma unroll
    for (int nf = 0; nf < 8; nf++)
#pragma unroll
        for (int c = 0; c < 4; c++) sacc[nf][c] = 0.f;

#pragma unroll
    for (int kc = 0; kc < 4; kc++) {
        uint4 afr;
        afr.x = qs[rA * 36 + kc * 8 + tig];
        afr.y = qs[rB * 36 + kc * 8 + tig];
        afr.z = qs[rA * 36 + kc * 8 + tig + 4];
        afr.w = qs[rB * 36 + kc * 8 + tig + 4];
#pragma unroll
        for (int nf = 0; nf < 8; nf++) {
            unsigned bb0 = ks[(nf * 8 + gid) * 36 + kc * 8 + tig];
            unsigned bb1 = ks[(nf * 8 + gid) * 36 + kc * 8 + tig + 4];
            mma_tf32(sacc[nf], afr, bb0, bb1);
        }
    }

    // ---- softmax rows rA (c0,c1) / rB (c2,c3); scale 1/sqrt(32) ----
    const float scl = 0.17677669529663687f;
    float mA = -1e30f, mB = -1e30f;
#pragma unroll
    for (int nf = 0; nf < 8; nf++) {
        sacc[nf][0] *= scl; sacc[nf][1] *= scl;
        sacc[nf][2] *= scl; sacc[nf][3] *= scl;
        mA = fmaxf(mA, fmaxf(sacc[nf][0], sacc[nf][1]));
        mB = fmaxf(mB, fmaxf(sacc[nf][2], sacc[nf][3]));
    }
#pragma unroll
    for (int o = 2; o > 0; o >>= 1) {
        mA = fmaxf(mA, __shfl_xor_sync(0xffffffffu, mA, o));
        mB = fmaxf(mB, __shfl_xor_sync(0xffffffffu, mB, o));
    }
    float sA = 0.f, sB = 0.f;
#pragma unroll
    for (int nf = 0; nf < 8; nf++) {
        sacc[nf][0] = __expf(sacc[nf][0] - mA); sA += sacc[nf][0];
        sacc[nf][1] = __expf(sacc[nf][1] - mA); sA += sacc[nf][1];
        sacc[nf][2] = __expf(sacc[nf][2] - mB); sB += sacc[nf][2];
        sacc[nf][3] = __expf(sacc[nf][3] - mB); sB += sacc[nf][3];
    }
#pragma unroll
    for (int o = 2; o > 0; o >>= 1) {
        sA += __shfl_xor_sync(0xffffffffu, sA, o);
        sB += __shfl_xor_sync(0xffffffffu, sB, o);
    }
    const float iA = 1.0f / sA, iB = 1.0f / sB;

    __syncthreads();   // all warps done reading qs/ks -> safe to overlay smP

    // ---- write P (tf32) to smP[row][key], stride 68 ----
#pragma unroll
    for (int nf = 0; nf < 8; nf++) {
        int col = nf * 8 + 2 * tig;
        uint2 pa = make_uint2(f2tf32(sacc[nf][0] * iA), f2tf32(sacc[nf][1] * iA));
        uint2 pb = make_uint2(f2tf32(sacc[nf][2] * iB), f2tf32(sacc[nf][3] * iB));
        *(uint2*)&smP[rA * 68 + col] = pa;
        *(uint2*)&smP[rB * 68 + col] = pb;
    }
    __syncthreads();

    // ---- PV: O[16 x 32] per warp, k=64 (8 steps), 4 n-frags ----
    float oacc[4][4];
#pragma unroll
    for (int nf = 0; nf < 4; nf++)
#pragma unroll
        for (int c = 0; c < 4; c++) oacc[nf][c] = 0.f;

#pragma unroll
    for (int kc = 0; kc < 8; kc++) {
        uint4 afr;
        afr.x = smP[rA * 68 + kc * 8 + tig];
        afr.y = smP[rB * 68 + kc * 8 + tig];
        afr.z = smP[rA * 68 + kc * 8 + tig + 4];
        afr.w = smP[rB * 68 + kc * 8 + tig + 4];
#pragma unroll
        for (int nf = 0; nf < 4; nf++) {
            unsigned bb0 = vs[(kc * 8 + tig) * 40 + nf * 8 + gid];
            unsigned bb1 = vs[(kc * 8 + tig + 4) * 40 + nf * 8 + gid];
            mma_tf32(oacc[nf], afr, bb0, bb1);
        }
    }

    // ---- store O/3 to this config's buffer ----
    const float third = 1.0f / 3.0f;
    const int tokA = base + off + r * rA;
    const int tokB = base + off + r * rB;
#pragma unroll
    for (int nf = 0; nf < 4; nf++) {
        int col = h * HDIM + nf * 8 + 2 * tig;
        *(float2*)&buf[(size_t)tokA * DIM + col] =
            make_float2(oacc[nf][0] * third, oacc[nf][1] * third);
        *(float2*)&buf[(size_t)tokB * DIM + col] =
            make_float2(oacc[nf][2] * third, oacc[nf][3] * third);
    }
}

// ---------------------------------------------------------------------------
// Layer-2 fused tail (per batch): q gemv, token-0 attn, Wo+res, LN2, FFN, LNf.
// ---------------------------------------------------------------------------
__global__ __launch_bounds__(256)
void tail_kernel(const float* __restrict__ x,  const float* __restrict__ hh,
                 const float* __restrict__ k,  const float* __restrict__ v,
                 const float* __restrict__ Wq, const float* __restrict__ Wo,
                 const float* __restrict__ W1, const float* __restrict__ W2,
                 const float* __restrict__ b1v, const float* __restrict__ b2v,
                 const float* __restrict__ ln2s, const float* __restrict__ ln2b,
                 const float* __restrict__ lnfs, const float* __restrict__ lnfb,
                 float* __restrict__ out)
{
    __shared__ float xs[256], hq[256], qsh[256], att[256], x1[256], h2[256];
    __shared__ float f[1024];
    __shared__ float red[4 * 256];
    __shared__ float psh[8][64];
    __shared__ float rsum[8];

    const int b    = blockIdx.x;
    const int t    = threadIdx.x;
    const int lane = t & 31;
    const int wrp  = t >> 5;
    const size_t row0 = (size_t)b * SEQ * DIM;

    xs[t] = x[row0 + t];
    hq[t] = hh[row0 + t];
    __syncthreads();

    // ---- q = hq @ Wq (split-K x4) ----
    {
        const int c4 = (t & 63) * 4;
        const int ks = t >> 6;
        float4 a = make_float4(0.f, 0.f, 0.f, 0.f);
        for (int kk = 0; kk < 64; kk++) {
            int ki = ks * 64 + kk;
            float s = hq[ki];
            float4 w = *(const float4*)&Wq[(size_t)ki * 256 + c4];
            a.x += s * w.x; a.y += s * w.y; a.z += s * w.z; a.w += s * w.w;
        }
        *(float4*)&red[ks * 256 + c4] = a;
        __syncthreads();
        qsh[t] = red[t] + red[256 + t] + red[512 + t] + red[768 + t];
        __syncthreads();
    }

    // ---- token-0 dilated attention ----
    {
        const int h = wrp;
        float o = 0.f;
        const float4* qv = (const float4*)&qsh[h * 32];
#pragma unroll
        for (int c = 0; c < 3; c++) {
            const int r = 1 << c;
            if (h % r == 0) {
                const float4* k0p = (const float4*)(k + ((size_t)(b * 256 + r * lane) * DIM) + h * 32);
                const float4* k1p = (const float4*)(k + ((size_t)(b * 256 + r * (lane + 32)) * DIM) + h * 32);
                float s0 = 0.f, s1 = 0.f;
#pragma unroll
                for (int u = 0; u < 8; u++) {
                    float4 qd = qv[u];
                    float4 ka = k0p[u];
                    float4 kb = k1p[u];
                    s0 += qd.x * ka.x + qd.y * ka.y + qd.z * ka.z + qd.w * ka.w;
                    s1 += qd.x * kb.x + qd.y * kb.y + qd.z * kb.z + qd.w * kb.w;
                }
                s0 *= 0.17677669529663687f;
                s1 *= 0.17677669529663687f;
                float mx = fmaxf(s0, s1);
#pragma unroll
                for (int ofs = 16; ofs > 0; ofs >>= 1)
                    mx = fmaxf(mx, __shfl_xor_sync(0xffffffffu, mx, ofs));
                float e0 = __expf(s0 - mx), e1 = __expf(s1 - mx);
                float sm = wred_sum(e0 + e1);
                float inv = 1.0f / sm;
                psh[h][lane]      = e0 * inv;
                psh[h][lane + 32] = e1 * inv;
                __syncwarp();
                float oc = 0.f;
#pragma unroll 8
                for (int j = 0; j < 64; j++)
                    oc += psh[h][j] * v[((size_t)(b * 256 + r * j) * DIM) + h * 32 + lane];
                o += oc;
                __syncwarp();
            }
        }
        att[h * 32 + lane] = o * (1.0f / 3.0f);
    }
    __syncthreads();

    // ---- x1 = att @ Wo + xs ----
    {
        const int c4 = (t & 63) * 4;
        const int ks = t >> 6;
        float4 a = make_float4(0.f, 0.f, 0.f, 0.f);
        for (int kk = 0; kk < 64; kk++) {
            int ki = ks * 64 + kk;
            float s = att[ki];
            float4 w = *(const float4*)&Wo[(size_t)ki * 256 + c4];
            a.x += s * w.x; a.y += s * w.y; a.z += s * w.z; a.w += s * w.w;
        }
        __syncthreads();
        *(float4*)&red[ks * 256 + c4] = a;
        __syncthreads();
        x1[t] = red[t] + red[256 + t] + red[512 + t] + red[768 + t] + xs[t];
        __syncthreads();
    }

    // ---- h2 = LN2(x1) ----
    {
        float val = x1[t];
        float s = wred_sum(val);
        if (lane == 0) rsum[wrp] = s;
        __syncthreads();
        float tot = 0.f;
#pragma unroll
        for (int i = 0; i < 8; i++) tot += rsum[i];
        float mu = tot * (1.0f / 256.0f);
        __syncthreads();
        float dv = val - mu;
        float s2 = wred_sum(dv * dv);
        if (lane == 0) rsum[wrp] = s2;
        __syncthreads();
        float tv = 0.f;
#pragma unroll
        for (int i = 0; i < 8; i++) tv += rsum[i];
        float inv = rsqrtf(tv * (1.0f / 256.0f) + 1e-5f);
        h2[t] = dv * inv * ln2s[t] + ln2b[t];
        __syncthreads();
    }

    // ---- f = gelu(h2 @ W1 + b1) ----
    {
        const int c4 = t * 4;
        float4 a = make_float4(0.f, 0.f, 0.f, 0.f);
        for (int ki = 0; ki < 256; ki++) {
            float s = h2[ki];
            float4 w = *(const float4*)&W1[(size_t)ki * 1024 + c4];
            a.x += s * w.x; a.y += s * w.y; a.z += s * w.z; a.w += s * w.w;
        }
        float4 bb = *(const float4*)&b1v[c4];
        f[c4 + 0] = gelu_tanh(a.x + bb.x);
        f[c4 + 1] = gelu_tanh(a.y + bb.y);
        f[c4 + 2] = gelu_tanh(a.z + bb.z);
        f[c4 + 3] = gelu_tanh(a.w + bb.w);
        __syncthreads();
    }

    // ---- y = f @ W2 + b2 + x1 ; out = LNf(y) ----
    {
        const int c4 = (t & 63) * 4;
        const int ks = t >> 6;
        float4 a = make_float4(0.f, 0.f, 0.f, 0.f);
        for (int kk = 0; kk < 256; kk++) {
            int ki = ks * 256 + kk;
            float s = f[ki];
            float4 w = *(const float4*)&W2[(size_t)ki * 256 + c4];
            a.x += s * w.x; a.y += s * w.y; a.z += s * w.z; a.w += s * w.w;
        }
        *(float4*)&red[ks * 256 + c4] = a;
        __syncthreads();
        float y = red[t] + red[256 + t] + red[512 + t] + red[768 + t] + b2v[t] + x1[t];

        float s = wred_sum(y);
        if (lane == 0) rsum[wrp] = s;
        __syncthreads();
        float tot = 0.f;
#pragma unroll
        for (int i = 0; i < 8; i++) tot += rsum[i];
        float mu = tot * (1.0f / 256.0f);
        __syncthreads();
        float dv = y - mu;
        float s2 = wred_sum(dv * dv);
        if (lane == 0) rsum[wrp] = s2;
        __syncthreads();
        float tv = 0.f;
#pragma unroll
        for (int i = 0; i < 8; i++) tv += rsum[i];
        float inv = rsqrtf(tv * (1.0f / 256.0f) + 1e-5f);
        out[(size_t)b * 256 + t] = dv * inv * lnfs[t] + lnfb[t];
    }
}

// ---------------------------------------------------------------------------
// Orchestration
// ---------------------------------------------------------------------------
extern "C" void kernel_launch(void* const* d_in, const int* in_sizes, int n_in,
                              void* d_out, int out_size)
{
    const float* target_feat   = (const float*)d_in[0];
    const float* context_feats = (const float*)d_in[1];
    const float* target_pos    = (const float*)d_in[2];
    const float* context_pos   = (const float*)d_in[3];
    const float* W_proj        = (const float*)d_in[4];
    const float* b_proj        = (const float*)d_in[5];
    const float* Wq            = (const float*)d_in[6];
    const float* Wk            = (const float*)d_in[7];
    const float* Wv            = (const float*)d_in[8];
    const float* Wo            = (const float*)d_in[9];
    const float* ln1_s         = (const float*)d_in[10];
    const float* ln1_b         = (const float*)d_in[11];
    const float* ln2_s         = (const float*)d_in[12];
    const float* ln2_b         = (const float*)d_in[13];
    const float* W1            = (const float*)d_in[14];
    const float* b1            = (const float*)d_in[15];
    const float* W2            = (const float*)d_in[16];
    const float* b2            = (const float*)d_in[17];
    const float* lnf_s         = (const float*)d_in[18];
    const float* lnf_b         = (const float*)d_in[19];
    float* out = (float*)d_out;

    float *x, *h, *q, *k, *v, *accb, *ffn;
    cudaGetSymbolAddress((void**)&x,    g_x);
    cudaGetSymbolAddress((void**)&h,    g_h);
    cudaGetSymbolAddress((void**)&q,    g_q);
    cudaGetSymbolAddress((void**)&k,    g_k);
    cudaGetSymbolAddress((void**)&v,    g_v);
    cudaGetSymbolAddress((void**)&accb, g_acc);
    cudaGetSymbolAddress((void**)&ffn,  g_ffn);

    const dim3 blk(256);
    const dim3 gN64 (DIM / 64, TOK / 64, 1);
    const dim3 gQKV (DIM / 64, TOK / 64, 3);
    const dim3 gKV  (DIM / 64, TOK / 64, 2);
    const dim3 gFFN1(FFN_DIM / 128, TOK / 64, 1);

    // 1. Projection (+bias +posenc fused), K=512
    mma_gemm<5, 64, true, false><<<gN64, blk>>>(
        nullptr, nullptr, nullptr, W_proj, nullptr, nullptr,
        b_proj, nullptr, x, nullptr, nullptr, DIM, INDIM,
        target_feat, context_feats, target_pos, context_pos);

    // ======================= Layer 1 (full) =======================
    ln_kernel<<<(TOK * 32) / 256, 256>>>(x, ln1_s, ln1_b, h, TOK, DIM);

    mma_gemm<0, 64, false, false><<<gQKV, blk>>>(
        h, nullptr, nullptr, Wq, Wk, Wv,
        nullptr, nullptr, q, k, v, DIM, DIM,
        nullptr, nullptr, nullptr, nullptr);

    attn_all_kernel<<<896, 128>>>(q, k, v, accb, h, ffn);

    mma_gemm<3, 64, false, true><<<gN64, blk>>>(
        accb, h, ffn, Wo, nullptr, nullptr,
        nullptr, x, x, nullptr, nullptr, DIM, DIM,
        nullptr, nullptr, nullptr, nullptr);

    ln_kernel<<<(TOK * 32) / 256, 256>>>(x, ln2_s, ln2_b, h, TOK, DIM);

    mma_gemm<2, 128, false, false><<<gFFN1, blk>>>(
        h, nullptr, nullptr, W1, nullptr, nullptr,
        b1, nullptr, ffn, nullptr, nullptr, FFN_DIM, DIM,
        nullptr, nullptr, nullptr, nullptr);

    mma_gemm<3, 64, false, false><<<gN64, blk>>>(
        ffn, nullptr, nullptr, W2, nullptr, nullptr,
        b2, x, x, nullptr, nullptr, DIM, FFN_DIM,
        nullptr, nullptr, nullptr, nullptr);

    // ================== Layer 2 (token-0 truncated) ==================
    ln_kernel<<<(TOK * 32) / 256, 256>>>(x, ln1_s + DIM, ln1_b + DIM, h, TOK, DIM);

    mma_gemm<0, 64, false, false><<<gKV, blk>>>(
        h, nullptr, nullptr, Wk + DIM * DIM, Wv + DIM * DIM, nullptr,
        nullptr, nullptr, k, v, nullptr, DIM, DIM,
        nullptr, nullptr, nullptr, nullptr);

    tail_kernel<<<BATCH, blk>>>(
        x, h, k, v,
        Wq + DIM * DIM, Wo + DIM * DIM,
        W1 + DIM * FFN_DIM, W2 + FFN_DIM * DIM,
        b1 + FFN_DIM, b2 + DIM,
        ln2_s + DIM, ln2_b + DIM, lnf_s, lnf_b, out);
}

// round 8
// speedup vs baseline: 3.2109x; 1.0676x over previous
#include <cuda_runtime.h>
#include <math.h>

// ---------------------------------------------------------------------------
// GlobalLocalAwareEncoder — truncated-dependency implementation.
// T1: dilated segments (64/128/256) never cross 256-token boundaries ->
//     output token 0 depends only on tokens [0,256) per batch.
// T2: layer 2 is last -> only token 0 per batch feeds output; layer-2 tail
//     fused into one 16-CTA kernel.
// Attention configs write disjoint buffers (t==h mod r); Wo sums with masks.
// Attention runs on tf32 m16n8k8 tensor cores (128-thread CTAs, 4 warps).
// All GEMMs use BN=128 CTA tiles (warp tile 32x32, 16 MMA/chunk/warp).
// ---------------------------------------------------------------------------

#define BATCH   16
#define SEQ     256
#define TOK     (BATCH * SEQ)   // 4096
#define DIM     256
#define HEADS   8
#define HDIM    32
#define FFN_DIM 1024
#define INDIM   512
#define NCTX    4095

__device__ float g_x  [TOK * DIM];
__device__ float g_h  [TOK * DIM];
__device__ float g_q  [TOK * DIM];
__device__ float g_k  [TOK * DIM];
__device__ float g_v  [TOK * DIM];
__device__ float g_acc[TOK * DIM];
__device__ float g_ffn[TOK * FFN_DIM];

__device__ __forceinline__ float gelu_tanh(float x) {
    float x3 = x * x * x;
    return 0.5f * x * (1.0f + tanhf(0.7978845608028654f * (x + 0.044715f * x3)));
}

__device__ __forceinline__ unsigned f2tf32(float f) {
    unsigned u;
    asm("cvt.rna.tf32.f32 %0, %1;" : "=r"(u) : "f"(f));
    return u;
}

__device__ __forceinline__ void mma_tf32(float* d, uint4 a, unsigned b0, unsigned b1) {
    asm volatile(
        "mma.sync.aligned.m16n8k8.row.col.f32.tf32.tf32.f32 "
        "{%0,%1,%2,%3}, {%4,%5,%6,%7}, {%8,%9}, {%0,%1,%2,%3};"
        : "+f"(d[0]), "+f"(d[1]), "+f"(d[2]), "+f"(d[3])
        : "r"(a.x), "r"(a.y), "r"(a.z), "r"(a.w), "r"(b0), "r"(b1));
}

__device__ __forceinline__ float wred_sum(float v) {
#pragma unroll
    for (int o = 16; o > 0; o >>= 1) v += __shfl_xor_sync(0xffffffffu, v, o);
    return v;
}

// positional encoding value for (token row, channel col), dim=256
__device__ __forceinline__ float pe_val(int row, int col,
                                        const float* __restrict__ tpos,
                                        const float* __restrict__ cpos) {
    int b = row >> 8, s = row & 255;
    const float* pp = (s == 0) ? (tpos + (size_t)b * 2)
                               : (cpos + ((size_t)b * NCTX + (s - 1)) * 2);
    float pos = (col < 128) ? pp[0] : pp[1];
    int dd = col & 127;
    int i  = dd & 63;
    float omega = expf(-(float)i * (9.210340371976184f / 64.0f));
    float ang = pos * omega;
    return (dd < 64) ? sinf(ang) : cosf(ang);
}

// ---------------------------------------------------------------------------
// tf32 MMA GEMM. C[4096,N] = A[4096,K] @ B[K,N], B row-major.
// CTA tile 64(M) x BN(N), BK=16, double-buffered. 8 warps, warp 32 x (BN/4).
// EPI: 0 store / 2 gelu(v+bias) / 3 v+res(+bias) / 5 v+bias+0.3*posenc
// ASUM3: A(t,k) = A1 + [t==h mod2]*A2 + [t==h mod4]*A4, h=k>>5.
// ---------------------------------------------------------------------------
template<int EPI, int BN, bool GATHER, bool ASUM3>
__global__ __launch_bounds__(256)
void mma_gemm(const float* __restrict__ A,
              const float* __restrict__ A2, const float* __restrict__ A4,
              const float* __restrict__ B0, const float* __restrict__ B1,
              const float* __restrict__ B2,
              const float* __restrict__ bias, const float* __restrict__ res,
              float* __restrict__ C0, float* __restrict__ C1, float* __restrict__ C2,
              int N, int K,
              const float* __restrict__ tfeat, const float* __restrict__ cfeat,
              const float* __restrict__ tpos,  const float* __restrict__ cpos)
{
    constexpr int BSST = BN + 8;
    constexpr int NF   = BN / 32;
    constexpr int NBL  = BN / 16;

    __shared__ unsigned As[2][1024];
    __shared__ unsigned Bs[2][16 * BSST];

    const int z = blockIdx.z;
    const float* B = (z == 0) ? B0 : (z == 1) ? B1 : B2;
    float*       C = (z == 0) ? C0 : (z == 1) ? C1 : C2;

    const int t    = threadIdx.x;
    const int lane = t & 31;
    const int warp = t >> 5;
    const int wm   = warp >> 2;
    const int wn   = warp & 3;
    const int gid  = lane >> 2;
    const int tig  = lane & 3;

    const int bm = blockIdx.y * 64;
    const int bn = blockIdx.x * BN;

    const int a_mf = t >> 6;
    const int al   = t & 31;
    const int arow = a_mf * 16 + (al >> 2);
    const int acol = ((t >> 5) & 1) * 8 + (al & 3);

    const int r0row = bm + arow;
    const int r1row = r0row + 8;

    const float *a1p0, *a1p1;
    const float *a2p0 = nullptr, *a2p1 = nullptr, *a4p0 = nullptr, *a4p1 = nullptr;
    if (GATHER) {
        int b0i = r0row >> 8, s0 = r0row & 255;
        int b1i = r1row >> 8, s1 = r1row & 255;
        a1p0 = (s0 == 0) ? (tfeat + (size_t)b0i * INDIM)
                         : (cfeat + ((size_t)b0i * NCTX + (s0 - 1)) * INDIM);
        a1p1 = (s1 == 0) ? (tfeat + (size_t)b1i * INDIM)
                         : (cfeat + ((size_t)b1i * NCTX + (s1 - 1)) * INDIM);
    } else {
        a1p0 = A + (size_t)r0row * K;
        a1p1 = A + (size_t)r1row * K;
        if (ASUM3) {
            a2p0 = A2 + (size_t)r0row * K;  a2p1 = A2 + (size_t)r1row * K;
            a4p0 = A4 + (size_t)r0row * K;  a4p1 = A4 + (size_t)r1row * K;
        }
    }

    int b_goff[NBL], b_soff[NBL];
#pragma unroll
    for (int i = 0; i < NBL; i++) {
        int idx = t + 256 * i;
        int kk  = idx / BN;
        int n   = idx % BN;
        b_goff[i] = kk * N + bn + n;
        b_soff[i] = kk * BSST + n;
    }

    float accd[2][NF][4];
#pragma unroll
    for (int mf = 0; mf < 2; mf++)
#pragma unroll
        for (int nf = 0; nf < NF; nf++)
#pragma unroll
            for (int r = 0; r < 4; r++) accd[mf][nf][r] = 0.f;

    const int nchunks = K >> 4;
    float pa0, pa1, pa2, pa3;
    float pb[NBL];

    auto loadA = [&](int k0) {
        if (ASUM3) {
            int kc  = k0 + acol;
            int hh  = kc >> 5;
            bool m20 = ((r0row ^ hh) & 1) == 0, m40 = ((r0row ^ hh) & 3) == 0;
            bool m21 = ((r1row ^ hh) & 1) == 0, m41 = ((r1row ^ hh) & 3) == 0;
            pa0 = a1p0[kc]     + (m20 ? a2p0[kc]     : 0.f) + (m40 ? a4p0[kc]     : 0.f);
            pa1 = a1p1[kc]     + (m21 ? a2p1[kc]     : 0.f) + (m41 ? a4p1[kc]     : 0.f);
            pa2 = a1p0[kc + 4] + (m20 ? a2p0[kc + 4] : 0.f) + (m40 ? a4p0[kc + 4] : 0.f);
            pa3 = a1p1[kc + 4] + (m21 ? a2p1[kc + 4] : 0.f) + (m41 ? a4p1[kc + 4] : 0.f);
        } else {
            pa0 = a1p0[k0 + acol];     pa1 = a1p1[k0 + acol];
            pa2 = a1p0[k0 + acol + 4]; pa3 = a1p1[k0 + acol + 4];
        }
    };

    {
        loadA(0);
        const float* bp = B;
#pragma unroll
        for (int i = 0; i < NBL; i++) pb[i] = bp[b_goff[i]];
        unsigned* aw = &As[0][t * 4];
        aw[0] = f2tf32(pa0); aw[1] = f2tf32(pa1);
        aw[2] = f2tf32(pa2); aw[3] = f2tf32(pa3);
#pragma unroll
        for (int i = 0; i < NBL; i++) Bs[0][b_soff[i]] = f2tf32(pb[i]);
    }
    __syncthreads();

    for (int c = 0; c < nchunks; c++) {
        const int s = c & 1;
        const bool more = (c + 1 < nchunks);
        if (more) {
            int k0 = (c + 1) << 4;
            loadA(k0);
            const float* bp = B + (size_t)k0 * N;
#pragma unroll
            for (int i = 0; i < NBL; i++) pb[i] = bp[b_goff[i]];
        }

#pragma unroll
        for (int kf = 0; kf < 2; kf++) {
            uint4 afr[2];
            afr[0] = *(const uint4*)&As[s][(((wm * 2 + 0) * 2 + kf) * 32 + lane) * 4];
            afr[1] = *(const uint4*)&As[s][(((wm * 2 + 1) * 2 + kf) * 32 + lane) * 4];
#pragma unroll
            for (int nf = 0; nf < NF; nf++) {
                int cb = wn * (BN / 4) + nf * 8 + gid;
                unsigned bb0 = Bs[s][(kf * 8 + tig) * BSST + cb];
                unsigned bb1 = Bs[s][(kf * 8 + tig + 4) * BSST + cb];
                mma_tf32(accd[0][nf], afr[0], bb0, bb1);
                mma_tf32(accd[1][nf], afr[1], bb0, bb1);
            }
        }

        if (more) {
            const int s2 = s ^ 1;
            unsigned* aw = &As[s2][t * 4];
            aw[0] = f2tf32(pa0); aw[1] = f2tf32(pa1);
            aw[2] = f2tf32(pa2); aw[3] = f2tf32(pa3);
#pragma unroll
            for (int i = 0; i < NBL; i++) Bs[s2][b_soff[i]] = f2tf32(pb[i]);
        }
        __syncthreads();
    }

#pragma unroll
    for (int mf = 0; mf < 2; mf++) {
#pragma unroll
        for (int nf = 0; nf < NF; nf++) {
            int row = bm + wm * 32 + mf * 16 + gid;
            int col = bn + wn * (BN / 4) + nf * 8 + 2 * tig;
#pragma unroll
            for (int half = 0; half < 2; half++) {
                int r = row + half * 8;
                float v0 = accd[mf][nf][half * 2 + 0];
                float v1 = accd[mf][nf][half * 2 + 1];
                size_t idx = (size_t)r * N + col;
                if (EPI == 2) {
                    v0 = gelu_tanh(v0 + bias[col]);
                    v1 = gelu_tanh(v1 + bias[col + 1]);
                } else if (EPI == 3) {
                    if (bias) { v0 += bias[col]; v1 += bias[col + 1]; }
                    v0 += res[idx]; v1 += res[idx + 1];
                } else if (EPI == 5) {
                    v0 += bias[col]     + 0.3f * pe_val(r, col,     tpos, cpos);
                    v1 += bias[col + 1] + 0.3f * pe_val(r, col + 1, tpos, cpos);
                }
                *(float2*)&C[idx] = make_float2(v0, v1);
            }
        }
    }
}

// ---------------------------------------------------------------------------
// LayerNorm: one warp per token, D=256.
// ---------------------------------------------------------------------------
__global__ void ln_kernel(const float* __restrict__ x, const float* __restrict__ sc,
                          const float* __restrict__ bi, float* __restrict__ out,
                          int ntok, int in_stride)
{
    int gw   = (blockIdx.x * blockDim.x + threadIdx.x) >> 5;
    int lane = threadIdx.x & 31;
    if (gw >= ntok) return;
    const float* xp = x + (size_t)gw * in_stride;
    float4 v0 = *(const float4*)&xp[lane * 4];
    float4 v1 = *(const float4*)&xp[128 + lane * 4];
    float va[8] = {v0.x, v0.y, v0.z, v0.w, v1.x, v1.y, v1.z, v1.w};

    float s = 0.f;
#pragma unroll
    for (int c = 0; c < 8; c++) s += va[c];
    s = wred_sum(s);
    float mu = s * (1.0f / 256.0f);

    float ss = 0.f;
#pragma unroll
    for (int c = 0; c < 8; c++) { float d = va[c] - mu; ss += d * d; }
    ss = wred_sum(ss);
    float inv = rsqrtf(ss * (1.0f / 256.0f) + 1e-5f);

    float ovals[8];
#pragma unroll
    for (int c = 0; c < 8; c++) {
        int d = (c < 4) ? (lane * 4 + c) : (128 + lane * 4 + (c - 4));
        ovals[c] = (va[c] - mu) * inv * sc[d] + bi[d];
    }
    float* op = out + (size_t)gw * 256;
    *(float4*)&op[lane * 4]       = make_float4(ovals[0], ovals[1], ovals[2], ovals[3]);
    *(float4*)&op[128 + lane * 4] = make_float4(ovals[4], ovals[5], ovals[6], ovals[7]);
}

// ---------------------------------------------------------------------------
// Layer-1 dilated attention on tf32 tensor cores. One launch, grid 896,
// 128 threads (4 warps; warp w owns rows 16w..16w+15 — 64 rows total).
// bid<512: (w=64,r=1)->b1; <768: (w=128,r=2)->b2; else (w=256,r=4)->b4.
// S = Q(64x32) K^T -> softmax in regs -> O = P(64x64) V(64x32).
// smem strides: Q/K 36, V 40, P 68. smP overlays Q/K after the QK phase.
// ---------------------------------------------------------------------------
__global__ __launch_bounds__(128)
void attn_all_kernel(const float* __restrict__ q, const float* __restrict__ k,
                     const float* __restrict__ v,
                     float* __restrict__ b1, float* __restrict__ b2,
                     float* __restrict__ b4)
{
    __shared__ unsigned sh[64 * 36 * 2 + 64 * 40];   // 7168 words = 28KB
    unsigned* qs  = sh;                 // [64][36]
    unsigned* ks  = sh + 64 * 36;       // [64][36]
    unsigned* vs  = sh + 64 * 72;       // [64][40]
    unsigned* smP = sh;                 // [64][68] overlays qs+ks (4352 <= 4608)

    int bid = blockIdx.x;
    int r, w;
    float* buf;
    if (bid < 512)      { w = 64;  r = 1; buf = b1; }
    else if (bid < 768) { bid -= 512; w = 128; r = 2; buf = b2; }
    else                { bid -= 768; w = 256; r = 4; buf = b4; }

    const int nseg = SEQ / w;
    const int h   = bid & 7;
    const int seg = (bid >> 3) % nseg;
    const int b   = bid / (8 * nseg);
    const int base = b * SEQ + seg * w;
    const int off  = h % r;
    const int t    = threadIdx.x;
    const int lane = t & 31;
    const int wrp  = t >> 5;             // 0..3
    const int gid  = lane >> 2;          // 0..7
    const int tig  = lane & 3;           // 0..3

    // ---- fill Q,K,V (tf32-converted): 512 float4 per array, 128 threads ----
#pragma unroll
    for (int i = 0; i < 4; i++) {
        int idx = t + 128 * i;          // 0..511
        int j  = idx >> 3;
        int dq = (idx & 7) * 4;
        int tok = base + off + r * j;
        size_t gi = (size_t)tok * DIM + h * HDIM + dq;
        float4 qv = *(const float4*)&q[gi];
        float4 kv = *(const float4*)&k[gi];
        float4 vv = *(const float4*)&v[gi];
        uint4 qu = make_uint4(f2tf32(qv.x), f2tf32(qv.y), f2tf32(qv.z), f2tf32(qv.w));
        uint4 ku = make_uint4(f2tf32(kv.x), f2tf32(kv.y), f2tf32(kv.z), f2tf32(kv.w));
        uint4 vu = make_uint4(f2tf32(vv.x), f2tf32(vv.y), f2tf32(vv.z), f2tf32(vv.w));
        *(uint4*)&qs[j * 36 + dq] = qu;
        *(uint4*)&ks[j * 36 + dq] = ku;
        *(uint4*)&vs[j * 40 + dq] = vu;
    }
    __syncthreads();

    // ---- QK: S[16 rows x 64 cols] per warp, k=32 (4 steps) ----
    const int rA = wrp * 16 + gid;       // 0..55
    const int rB = rA + 8;               // 8..63
    float sacc[8][4];
#pragma unroll
    for (int nf = 0; nf < 8; nf++)
#pragma unroll
        for (int c = 0; c < 4; c++) sacc[nf][c] = 0.f;

#pragma unroll
    for (int kc = 0; kc < 4; kc++) {
        uint4 afr;
        afr.x = qs[rA * 36 + kc * 8 + tig];
        afr.y = qs[rB * 36 + kc * 8 + tig];
        afr.z = qs[rA * 36 + kc * 8 + tig + 4];
        afr.w = qs[rB * 36 + kc * 8 + tig + 4];
#pragma unroll
        for (int nf = 0; nf < 8; nf++) {
            unsigned bb0 = ks[(nf * 8 + gid) * 36 + kc * 8 + tig];
            unsigned bb1 = ks[(nf * 8 + gid) * 36 + kc * 8 + tig + 4];
            mma_tf32(sacc[nf], afr, bb0, bb1);
        }
    }

    // ---- softmax rows rA (c0,c1) / rB (c2,c3); scale 1/sqrt(32) ----
    const float scl = 0.17677669529663687f;
    float mA = -1e30f, mB = -1e30f;
#pragma unroll
    for (int nf = 0; nf < 8; nf++) {
        sacc[nf][0] *= scl; sacc[nf][1] *= scl;
        sacc[nf][2] *= scl; sacc[nf][3] *= scl;
        mA = fmaxf(mA, fmaxf(sacc[nf][0], sacc[nf][1]));
        mB = fmaxf(mB, fmaxf(sacc[nf][2], sacc[nf][3]));
    }
#pragma unroll
    for (int o = 2; o > 0; o >>= 1) {
        mA = fmaxf(mA, __shfl_xor_sync(0xffffffffu, mA, o));
        mB = fmaxf(mB, __shfl_xor_sync(0xffffffffu, mB, o));
    }
    float sA = 0.f, sB = 0.f;
#pragma unroll
    for (int nf = 0; nf < 8; nf++) {
        sacc[nf][0] = __expf(sacc[nf][0] - mA); sA += sacc[nf][0];
        sacc[nf][1] = __expf(sacc[nf][1] - mA); sA += sacc[nf][1];
        sacc[nf][2] = __expf(sacc[nf][2] - mB); sB += sacc[nf][2];
        sacc[nf][3] = __expf(sacc[nf][3] - mB); sB += sacc[nf][3];
    }
#pragma unroll
    for (int o = 2; o > 0; o >>= 1) {
        sA += __shfl_xor_sync(0xffffffffu, sA, o);
        sB += __shfl_xor_sync(0xffffffffu, sB, o);
    }
    const float iA = 1.0f / sA, iB = 1.0f / sB;

    __syncthreads();   // all warps done reading qs/ks -> safe to overlay smP

    // ---- write P (tf32) to smP[row][key], stride 68 ----
#pragma unroll
    for (int nf = 0; nf < 8; nf++) {
        int col = nf * 8 + 2 * tig;
        uint2 pa = make_uint2(f2tf32(sacc[nf][0] * iA), f2tf32(sacc[nf][1] * iA));
        uint2 pb = make_uint2(f2tf32(sacc[nf][2] * iB), f2tf32(sacc[nf][3] * iB));
        *(uint2*)&smP[rA * 68 + col] = pa;
        *(uint2*)&smP[rB * 68 + col] = pb;
    }
    __syncthreads();

    // ---- PV: O[16 x 32] per warp, k=64 (8 steps), 4 n-frags ----
    float oacc[4][4];
#pragma unroll
    for (int nf = 0; nf < 4; nf++)
#pragma unroll
        for (int c = 0; c < 4; c++) oacc[nf][c] = 0.f;

#pragma unroll
    for (int kc = 0; kc < 8; kc++) {
        uint4 afr;
        afr.x = smP[rA * 68 + kc * 8 + tig];
        afr.y = smP[rB * 68 + kc * 8 + tig];
        afr.z = smP[rA * 68 + kc * 8 + tig + 4];
        afr.w = smP[rB * 68 + kc * 8 + tig + 4];
#pragma unroll
        for (int nf = 0; nf < 4; nf++) {
            unsigned bb0 = vs[(kc * 8 + tig) * 40 + nf * 8 + gid];
            unsigned bb1 = vs[(kc * 8 + tig + 4) * 40 + nf * 8 + gid];
            mma_tf32(oacc[nf], afr, bb0, bb1);
        }
    }

    // ---- store O/3 to this config's buffer ----
    const float third = 1.0f / 3.0f;
    const int tokA = base + off + r * rA;
    const int tokB = base + off + r * rB;
#pragma unroll
    for (int nf = 0; nf < 4; nf++) {
        int col = h * HDIM + nf * 8 + 2 * tig;
        *(float2*)&buf[(size_t)tokA * DIM + col] =
            make_float2(oacc[nf][0] * third, oacc[nf][1] * third);
        *(float2*)&buf[(size_t)tokB * DIM + col] =
            make_float2(oacc[nf][2] * third, oacc[nf][3] * third);
    }
}

// ---------------------------------------------------------------------------
// Layer-2 fused tail (per batch): q gemv, token-0 attn, Wo+res, LN2, FFN, LNf.
// ---------------------------------------------------------------------------
__global__ __launch_bounds__(256)
void tail_kernel(const float* __restrict__ x,  const float* __restrict__ hh,
                 const float* __restrict__ k,  const float* __restrict__ v,
                 const float* __restrict__ Wq, const float* __restrict__ Wo,
                 const float* __restrict__ W1, const float* __restrict__ W2,
                 const float* __restrict__ b1v, const float* __restrict__ b2v,
                 const float* __restrict__ ln2s, const float* __restrict__ ln2b,
                 const float* __restrict__ lnfs, const float* __restrict__ lnfb,
                 float* __restrict__ out)
{
    __shared__ float xs[256], hq[256], qsh[256], att[256], x1[256], h2[256];
    __shared__ float f[1024];
    __shared__ float red[4 * 256];
    __shared__ float psh[8][64];
    __shared__ float rsum[8];

    const int b    = blockIdx.x;
    const int t    = threadIdx.x;
    const int lane = t & 31;
    const int wrp  = t >> 5;
    const size_t row0 = (size_t)b * SEQ * DIM;

    xs[t] = x[row0 + t];
    hq[t] = hh[row0 + t];
    __syncthreads();

    // ---- q = hq @ Wq (split-K x4) ----
    {
        const int c4 = (t & 63) * 4;
        const int ks = t >> 6;
        float4 a = make_float4(0.f, 0.f, 0.f, 0.f);
        for (int kk = 0; kk < 64; kk++) {
            int ki = ks * 64 + kk;
            float s = hq[ki];
            float4 w = *(const float4*)&Wq[(size_t)ki * 256 + c4];
            a.x += s * w.x; a.y += s * w.y; a.z += s * w.z; a.w += s * w.w;
        }
        *(float4*)&red[ks * 256 + c4] = a;
        __syncthreads();
        qsh[t] = red[t] + red[256 + t] + red[512 + t] + red[768 + t];
        __syncthreads();
    }

    // ---- token-0 dilated attention ----
    {
        const int h = wrp;
        float o = 0.f;
        const float4* qv = (const float4*)&qsh[h * 32];
#pragma unroll
        for (int c = 0; c < 3; c++) {
            const int r = 1 << c;
            if (h % r == 0) {
                const float4* k0p = (const float4*)(k + ((size_t)(b * 256 + r * lane) * DIM) + h * 32);
                const float4* k1p = (const float4*)(k + ((size_t)(b * 256 + r * (lane + 32)) * DIM) + h * 32);
                float s0 = 0.f, s1 = 0.f;
#pragma unroll
                for (int u = 0; u < 8; u++) {
                    float4 qd = qv[u];
                    float4 ka = k0p[u];
                    float4 kb = k1p[u];
                    s0 += qd.x * ka.x + qd.y * ka.y + qd.z * ka.z + qd.w * ka.w;
                    s1 += qd.x * kb.x + qd.y * kb.y + qd.z * kb.z + qd.w * kb.w;
                }
                s0 *= 0.17677669529663687f;
                s1 *= 0.17677669529663687f;
                float mx = fmaxf(s0, s1);
#pragma unroll
                for (int ofs = 16; ofs > 0; ofs >>= 1)
                    mx = fmaxf(mx, __shfl_xor_sync(0xffffffffu, mx, ofs));
                float e0 = __expf(s0 - mx), e1 = __expf(s1 - mx);
                float sm = wred_sum(e0 + e1);
                float inv = 1.0f / sm;
                psh[h][lane]      = e0 * inv;
                psh[h][lane + 32] = e1 * inv;
                __syncwarp();
                float oc = 0.f;
#pragma unroll 8
                for (int j = 0; j < 64; j++)
                    oc += psh[h][j] * v[((size_t)(b * 256 + r * j) * DIM) + h * 32 + lane];
                o += oc;
                __syncwarp();
            }
        }
        att[h * 32 + lane] = o * (1.0f / 3.0f);
    }
    __syncthreads();

    // ---- x1 = att @ Wo + xs ----
    {
        const int c4 = (t & 63) * 4;
        const int ks = t >> 6;
        float4 a = make_float4(0.f, 0.f, 0.f, 0.f);
        for (int kk = 0; kk < 64; kk++) {
            int ki = ks * 64 + kk;
            float s = att[ki];
            float4 w = *(const float4*)&Wo[(size_t)ki * 256 + c4];
            a.x += s * w.x; a.y += s * w.y; a.z += s * w.z; a.w += s * w.w;
        }
        __syncthreads();
        *(float4*)&red[ks * 256 + c4] = a;
        __syncthreads();
        x1[t] = red[t] + red[256 + t] + red[512 + t] + red[768 + t] + xs[t];
        __syncthreads();
    }

    // ---- h2 = LN2(x1) ----
    {
        float val = x1[t];
        float s = wred_sum(val);
        if (lane == 0) rsum[wrp] = s;
        __syncthreads();
        float tot = 0.f;
#pragma unroll
        for (int i = 0; i < 8; i++) tot += rsum[i];
        float mu = tot * (1.0f / 256.0f);
        __syncthreads();
        float dv = val - mu;
        float s2 = wred_sum(dv * dv);
        if (lane == 0) rsum[wrp] = s2;
        __syncthreads();
        float tv = 0.f;
#pragma unroll
        for (int i = 0; i < 8; i++) tv += rsum[i];
        float inv = rsqrtf(tv * (1.0f / 256.0f) + 1e-5f);
        h2[t] = dv * inv * ln2s[t] + ln2b[t];
        __syncthreads();
    }

    // ---- f = gelu(h2 @ W1 + b1) ----
    {
        const int c4 = t * 4;
        float4 a = make_float4(0.f, 0.f, 0.f, 0.f);
        for (int ki = 0; ki < 256; ki++) {
            float s = h2[ki];
            float4 w = *(const float4*)&W1[(size_t)ki * 1024 + c4];
            a.x += s * w.x; a.y += s * w.y; a.z += s * w.z; a.w += s * w.w;
        }
        float4 bb = *(const float4*)&b1v[c4];
        f[c4 + 0] = gelu_tanh(a.x + bb.x);
        f[c4 + 1] = gelu_tanh(a.y + bb.y);
        f[c4 + 2] = gelu_tanh(a.z + bb.z);
        f[c4 + 3] = gelu_tanh(a.w + bb.w);
        __syncthreads();
    }

    // ---- y = f @ W2 + b2 + x1 ; out = LNf(y) ----
    {
        const int c4 = (t & 63) * 4;
        const int ks = t >> 6;
        float4 a = make_float4(0.f, 0.f, 0.f, 0.f);
        for (int kk = 0; kk < 256; kk++) {
            int ki = ks * 256 + kk;
            float s = f[ki];
            float4 w = *(const float4*)&W2[(size_t)ki * 256 + c4];
            a.x += s * w.x; a.y += s * w.y; a.z += s * w.z; a.w += s * w.w;
        }
        *(float4*)&red[ks * 256 + c4] = a;
        __syncthreads();
        float y = red[t] + red[256 + t] + red[512 + t] + red[768 + t] + b2v[t] + x1[t];

        float s = wred_sum(y);
        if (lane == 0) rsum[wrp] = s;
        __syncthreads();
        float tot = 0.f;
#pragma unroll
        for (int i = 0; i < 8; i++) tot += rsum[i];
        float mu = tot * (1.0f / 256.0f);
        __syncthreads();
        float dv = y - mu;
        float s2 = wred_sum(dv * dv);
        if (lane == 0) rsum[wrp] = s2;
        __syncthreads();
        float tv = 0.f;
#pragma unroll
        for (int i = 0; i < 8; i++) tv += rsum[i];
        float inv = rsqrtf(tv * (1.0f / 256.0f) + 1e-5f);
        out[(size_t)b * 256 + t] = dv * inv * lnfs[t] + lnfb[t];
    }
}

// ---------------------------------------------------------------------------
// Orchestration
// ---------------------------------------------------------------------------
extern "C" void kernel_launch(void* const* d_in, const int* in_sizes, int n_in,
                              void* d_out, int out_size)
{
    const float* target_feat   = (const float*)d_in[0];
    const float* context_feats = (const float*)d_in[1];
    const float* target_pos    = (const float*)d_in[2];
    const float* context_pos   = (const float*)d_in[3];
    const float* W_proj        = (const float*)d_in[4];
    const float* b_proj        = (const float*)d_in[5];
    const float* Wq            = (const float*)d_in[6];
    const float* Wk            = (const float*)d_in[7];
    const float* Wv            = (const float*)d_in[8];
    const float* Wo            = (const float*)d_in[9];
    const float* ln1_s         = (const float*)d_in[10];
    const float* ln1_b         = (const float*)d_in[11];
    const float* ln2_s         = (const float*)d_in[12];
    const float* ln2_b         = (const float*)d_in[13];
    const float* W1            = (const float*)d_in[14];
    const float* b1            = (const float*)d_in[15];
    const float* W2            = (const float*)d_in[16];
    const float* b2            = (const float*)d_in[17];
    const float* lnf_s         = (const float*)d_in[18];
    const float* lnf_b         = (const float*)d_in[19];
    float* out = (float*)d_out;

    float *x, *h, *q, *k, *v, *accb, *ffn;
    cudaGetSymbolAddress((void**)&x,    g_x);
    cudaGetSymbolAddress((void**)&h,    g_h);
    cudaGetSymbolAddress((void**)&q,    g_q);
    cudaGetSymbolAddress((void**)&k,    g_k);
    cudaGetSymbolAddress((void**)&v,    g_v);
    cudaGetSymbolAddress((void**)&accb, g_acc);
    cudaGetSymbolAddress((void**)&ffn,  g_ffn);

    const dim3 blk(256);
    const dim3 gN128 (DIM / 128, TOK / 64, 1);       // (2, 64)
    const dim3 gQKV  (DIM / 128, TOK / 64, 3);       // (2, 64, 3)
    const dim3 gKV   (DIM / 128, TOK / 64, 2);       // (2, 64, 2)
    const dim3 gFFN1 (FFN_DIM / 128, TOK / 64, 1);   // (8, 64)

    // 1. Projection (+bias +posenc fused), K=512
    mma_gemm<5, 128, true, false><<<gN128, blk>>>(
        nullptr, nullptr, nullptr, W_proj, nullptr, nullptr,
        b_proj, nullptr, x, nullptr, nullptr, DIM, INDIM,
        target_feat, context_feats, target_pos, context_pos);

    // ======================= Layer 1 (full) =======================
    ln_kernel<<<(TOK * 32) / 256, 256>>>(x, ln1_s, ln1_b, h, TOK, DIM);

    mma_gemm<0, 128, false, false><<<gQKV, blk>>>(
        h, nullptr, nullptr, Wq, Wk, Wv,
        nullptr, nullptr, q, k, v, DIM, DIM,
        nullptr, nullptr, nullptr, nullptr);

    attn_all_kernel<<<896, 128>>>(q, k, v, accb, h, ffn);

    mma_gemm<3, 128, false, true><<<gN128, blk>>>(
        accb, h, ffn, Wo, nullptr, nullptr,
        nullptr, x, x, nullptr, nullptr, DIM, DIM,
        nullptr, nullptr, nullptr, nullptr);

    ln_kernel<<<(TOK * 32) / 256, 256>>>(x, ln2_s, ln2_b, h, TOK, DIM);

    mma_gemm<2, 128, false, false><<<gFFN1, blk>>>(
        h, nullptr, nullptr, W1, nullptr, nullptr,
        b1, nullptr, ffn, nullptr, nullptr, FFN_DIM, DIM,
        nullptr, nullptr, nullptr, nullptr);

    mma_gemm<3, 128, false, false><<<gN128, blk>>>(
        ffn, nullptr, nullptr, W2, nullptr, nullptr,
        b2, x, x, nullptr, nullptr, DIM, FFN_DIM,
        nullptr, nullptr, nullptr, nullptr);

    // ================== Layer 2 (token-0 truncated) ==================
    ln_kernel<<<(TOK * 32) / 256, 256>>>(x, ln1_s + DIM, ln1_b + DIM, h, TOK, DIM);

    mma_gemm<0, 128, false, false><<<gKV, blk>>>(
        h, nullptr, nullptr, Wk + DIM * DIM, Wv + DIM * DIM, nullptr,
        nullptr, nullptr, k, v, nullptr, DIM, DIM,
        nullptr, nullptr, nullptr, nullptr);

    tail_kernel<<<BATCH, blk>>>(
        x, h, k, v,
        Wq + DIM * DIM, Wo + DIM * DIM,
        W1 + DIM * FFN_DIM, W2 + FFN_DIM * DIM,
        b1 + FFN_DIM, b2 + DIM,
        ln2_s + DIM, ln2_b + DIM, lnf_s, lnf_b, out);
}